// round 2
// baseline (speedup 1.0000x reference)
#include <cuda_runtime.h>

#define NN 50000
#define MM 800000
#define HH 64
#define EE 8
#define INN 16
#define DIN 137  // 1 + 2*H + E
#define LL 2
#define EPB 64   // edges per 256-thread block (4 threads/edge)
#define NPB 64   // nodes per 256-thread block

typedef unsigned long long u64;

// ---------------- device scratch (no allocs allowed) ----------------
__device__ float g_h0[NN * HH];
__device__ float g_h1[NN * HH];
__device__ float g_x[NN * 3];
__device__ float g_aggmsg[NN * HH];
__device__ float g_aggf[NN * 3];
__device__ float g_cnt[NN];

__device__ __forceinline__ float silu_f(float v) {
    return __fdividef(v, 1.0f + __expf(-v));
}

__device__ __forceinline__ u64 pack2(float s) {
    u64 r;
    asm("mov.b64 %0, {%1, %1};" : "=l"(r) : "f"(s));
    return r;
}
__device__ __forceinline__ void unpack2(u64 v, float& lo, float& hi) {
    asm("mov.b64 {%0, %1}, %2;" : "=f"(lo), "=f"(hi) : "l"(v));
}
__device__ __forceinline__ void fma2(u64& acc, u64 w, u64 s) {
    asm("fma.rn.f32x2 %0, %1, %2, %0;" : "+l"(acc) : "l"(w), "l"(s));
}

// acc (16 floats as 8 f32x2) += s * w[0..15]   (w in shared, 16B aligned)
__device__ __forceinline__ void fma16(u64* acc, u64 s2, const float* w) {
    const ulonglong2* w2 = reinterpret_cast<const ulonglong2*>(w);
#pragma unroll
    for (int q = 0; q < 4; q++) {
        ulonglong2 t = w2[q];
        fma2(acc[2 * q],     t.x, s2);
        fma2(acc[2 * q + 1], t.y, s2);
    }
}

__device__ __forceinline__ void load16(u64* acc, const float* b) {
    const ulonglong2* p = reinterpret_cast<const ulonglong2*>(b);
#pragma unroll
    for (int q = 0; q < 4; q++) {
        ulonglong2 v = p[q];
        acc[2 * q] = v.x;
        acc[2 * q + 1] = v.y;
    }
}

// ---------------- embedding: h0 = h @ embW + embB ----------------
__global__ void k_embed(const float* __restrict__ h_in,
                        const float* __restrict__ W,
                        const float* __restrict__ b) {
    __shared__ float sW[INN * HH];
    __shared__ float sb[HH];
    for (int i = threadIdx.x; i < INN * HH; i += blockDim.x) sW[i] = W[i];
    for (int i = threadIdx.x; i < HH; i += blockDim.x) sb[i] = b[i];
    __syncthreads();
    int idx = blockIdx.x * blockDim.x + threadIdx.x;
    int n = idx >> 2, sub = idx & 3, jo = sub * 16;
    if (n >= NN) return;
    u64 acc[8];
    load16(acc, sb + jo);
    const float4* hv = (const float4*)(h_in + (size_t)n * INN);
#pragma unroll
    for (int q = 0; q < INN / 4; q++) {
        float4 v = hv[q];
        fma16(acc, pack2(v.x), sW + (4 * q + 0) * HH + jo);
        fma16(acc, pack2(v.y), sW + (4 * q + 1) * HH + jo);
        fma16(acc, pack2(v.z), sW + (4 * q + 2) * HH + jo);
        fma16(acc, pack2(v.w), sW + (4 * q + 3) * HH + jo);
    }
    float4* outp = (float4*)(g_h0 + (size_t)n * HH + jo);
#pragma unroll
    for (int q = 0; q < 4; q++) {
        float a, bb, c, d;
        unpack2(acc[2 * q], a, bb);
        unpack2(acc[2 * q + 1], c, d);
        outp[q] = make_float4(a, bb, c, d);
    }
}

// ---------------- degree count ----------------
__global__ void k_cnt(const int* __restrict__ row) {
    int e = blockIdx.x * blockDim.x + threadIdx.x;
    if (e < MM) atomicAdd(&g_cnt[row[e]], 1.0f);
}

// ---------------- fused edge kernel (4 threads / edge) ----------------
// smem floats: W1[137*64] | W2[64*64] | CW1[64*64] | B1,B2,CB1,CW2 (64 ea) |
//              CB2(1,+3 pad) | stageH[64*68] | stageM[64*68]
#define EDGE_SMEM_FLOATS (DIN * HH + 2 * HH * HH + 4 * HH + 4 + 2 * EPB * 68)

__global__ __launch_bounds__(256, 2) void k_edge(
    const float* __restrict__ h_in,
    const int* __restrict__ row, const int* __restrict__ col,
    const float* __restrict__ efea,
    const float* __restrict__ W1, const float* __restrict__ B1,
    const float* __restrict__ W2, const float* __restrict__ B2,
    const float* __restrict__ CW1, const float* __restrict__ CB1,
    const float* __restrict__ CW2, const float* __restrict__ CB2) {
    extern __shared__ float sm[];
    float* sW1  = sm;                    // DIN*HH, k-major
    float* sW2  = sW1 + DIN * HH;        // HH*HH, k-major
    float* sCW1 = sW2 + HH * HH;         // HH*HH, k-major
    float* sB1  = sCW1 + HH * HH;
    float* sB2  = sB1 + HH;
    float* sCB1 = sB2 + HH;
    float* sCW2 = sCB1 + HH;
    float* sCB2 = sCW2 + HH;             // 1 + 3 pad
    float* stH  = sCB2 + 4;              // EPB rows of 68 (padded vs bank conflicts)
    float* stM  = stH + EPB * 68;

    const int t = threadIdx.x;
    for (int i = t; i < DIN * HH; i += 256) sW1[i] = W1[i];
    for (int i = t; i < HH * HH; i += 256) { sW2[i] = W2[i]; sCW1[i] = CW1[i]; }
    for (int i = t; i < HH; i += 256) {
        sB1[i] = B1[i]; sB2[i] = B2[i]; sCB1[i] = CB1[i]; sCW2[i] = CW2[i];
    }
    if (t == 0) sCB2[0] = CB2[0];
    __syncthreads();

    const int eL = t >> 2, sub = t & 3, jo = sub * 16;
    const int e = blockIdx.x * EPB + eL;   // MM % EPB == 0, no tail
    const int r = row[e], c = col[e];
    const float rx = g_x[r * 3 + 0] - g_x[c * 3 + 0];
    const float ry = g_x[r * 3 + 1] - g_x[c * 3 + 1];
    const float rz = g_x[r * 3 + 2] - g_x[c * 3 + 2];
    const float r2 = rx * rx + ry * ry + rz * rz;

    // ---- layer 1: hid = silu(s @ W1 + b1), this thread owns 16 outputs ----
    u64 acc[8];
    load16(acc, sB1 + jo);
    fma16(acc, pack2(r2), sW1 + jo);  // k = 0
    {
        const float4* hr = (const float4*)(h_in + (size_t)r * HH);
#pragma unroll
        for (int q = 0; q < 16; q++) {
            float4 v = hr[q];
            fma16(acc, pack2(v.x), sW1 + (1 + 4 * q + 0) * HH + jo);
            fma16(acc, pack2(v.y), sW1 + (1 + 4 * q + 1) * HH + jo);
            fma16(acc, pack2(v.z), sW1 + (1 + 4 * q + 2) * HH + jo);
            fma16(acc, pack2(v.w), sW1 + (1 + 4 * q + 3) * HH + jo);
        }
        const float4* hc = (const float4*)(h_in + (size_t)c * HH);
#pragma unroll
        for (int q = 0; q < 16; q++) {
            float4 v = hc[q];
            fma16(acc, pack2(v.x), sW1 + (1 + HH + 4 * q + 0) * HH + jo);
            fma16(acc, pack2(v.y), sW1 + (1 + HH + 4 * q + 1) * HH + jo);
            fma16(acc, pack2(v.z), sW1 + (1 + HH + 4 * q + 2) * HH + jo);
            fma16(acc, pack2(v.w), sW1 + (1 + HH + 4 * q + 3) * HH + jo);
        }
        const float4* ef = (const float4*)(efea + (size_t)e * EE);
#pragma unroll
        for (int q = 0; q < 2; q++) {
            float4 v = ef[q];
            fma16(acc, pack2(v.x), sW1 + (1 + 2 * HH + 4 * q + 0) * HH + jo);
            fma16(acc, pack2(v.y), sW1 + (1 + 2 * HH + 4 * q + 1) * HH + jo);
            fma16(acc, pack2(v.z), sW1 + (1 + 2 * HH + 4 * q + 2) * HH + jo);
            fma16(acc, pack2(v.w), sW1 + (1 + 2 * HH + 4 * q + 3) * HH + jo);
        }
    }
    {
        float4* myH = (float4*)(stH + eL * 68 + jo);
#pragma unroll
        for (int q = 0; q < 4; q++) {
            float a, b, cc, d;
            unpack2(acc[2 * q], a, b);
            unpack2(acc[2 * q + 1], cc, d);
            myH[q] = make_float4(silu_f(a), silu_f(b), silu_f(cc), silu_f(d));
        }
    }
    __syncwarp();

    // ---- layer 2: msg = silu(hid @ W2 + b2) ----
    load16(acc, sB2 + jo);
    {
        const float4* hs = (const float4*)(stH + eL * 68);
#pragma unroll
        for (int q = 0; q < 16; q++) {
            float4 v = hs[q];
            fma16(acc, pack2(v.x), sW2 + (4 * q + 0) * HH + jo);
            fma16(acc, pack2(v.y), sW2 + (4 * q + 1) * HH + jo);
            fma16(acc, pack2(v.z), sW2 + (4 * q + 2) * HH + jo);
            fma16(acc, pack2(v.w), sW2 + (4 * q + 3) * HH + jo);
        }
    }
    float msg[16];
#pragma unroll
    for (int q = 0; q < 4; q++) {
        float a, b, cc, d;
        unpack2(acc[2 * q], a, b);
        unpack2(acc[2 * q + 1], cc, d);
        msg[4 * q + 0] = silu_f(a);
        msg[4 * q + 1] = silu_f(b);
        msg[4 * q + 2] = silu_f(cc);
        msg[4 * q + 3] = silu_f(d);
    }
    {
        float* am = &g_aggmsg[(size_t)r * HH + jo];
#pragma unroll
        for (int j = 0; j < 16; j++) atomicAdd(am + j, msg[j]);
        float4* myM = (float4*)(stM + eL * 68 + jo);
#pragma unroll
        for (int q = 0; q < 4; q++)
            myM[q] = make_float4(msg[4 * q], msg[4 * q + 1], msg[4 * q + 2], msg[4 * q + 3]);
    }
    __syncwarp();

    // ---- coord net: cm = silu(msg @ CW1 + cb1) @ CW2 + cb2 ----
    load16(acc, sCB1 + jo);
    {
        const float4* ms = (const float4*)(stM + eL * 68);
#pragma unroll
        for (int q = 0; q < 16; q++) {
            float4 v = ms[q];
            fma16(acc, pack2(v.x), sCW1 + (4 * q + 0) * HH + jo);
            fma16(acc, pack2(v.y), sCW1 + (4 * q + 1) * HH + jo);
            fma16(acc, pack2(v.z), sCW1 + (4 * q + 2) * HH + jo);
            fma16(acc, pack2(v.w), sCW1 + (4 * q + 3) * HH + jo);
        }
    }
    float cm = 0.0f;
#pragma unroll
    for (int q = 0; q < 4; q++) {
        float a, b, cc, d;
        unpack2(acc[2 * q], a, b);
        unpack2(acc[2 * q + 1], cc, d);
        cm += silu_f(a) * sCW2[jo + 4 * q + 0];
        cm += silu_f(b) * sCW2[jo + 4 * q + 1];
        cm += silu_f(cc) * sCW2[jo + 4 * q + 2];
        cm += silu_f(d) * sCW2[jo + 4 * q + 3];
    }
    cm += __shfl_xor_sync(0xffffffffu, cm, 1);
    cm += __shfl_xor_sync(0xffffffffu, cm, 2);
    cm += sCB2[0];
    if (sub == 0)      atomicAdd(&g_aggf[r * 3 + 0], rx * cm);
    else if (sub == 1) atomicAdd(&g_aggf[r * 3 + 1], ry * cm);
    else if (sub == 2) atomicAdd(&g_aggf[r * 3 + 2], rz * cm);
}

// ---------------- node kernel (4 threads / node) ----------------
// smem floats: NW1[128*64] | NW2[64*64] | B1,B2 | stage[64*68]
#define NODE_SMEM_FLOATS (2 * HH * HH + HH * HH + 2 * HH + NPB * 68)

__global__ __launch_bounds__(256, 3) void k_node(
    const float* __restrict__ h_in, float* __restrict__ h_out,
    const float* __restrict__ NW1, const float* __restrict__ NB1,
    const float* __restrict__ NW2, const float* __restrict__ NB2,
    float* __restrict__ out_x, float* __restrict__ out_h, int writeOut) {
    extern __shared__ float sm[];
    float* sW1 = sm;                      // [2H][H] k-major
    float* sW2 = sW1 + 2 * HH * HH;       // [H][H] k-major
    float* sB1 = sW2 + HH * HH;
    float* sB2 = sB1 + HH;
    float* stH = sB2 + HH;                // NPB * 68

    const int t = threadIdx.x;
    for (int i = t; i < 2 * HH * HH; i += 256) sW1[i] = NW1[i];
    for (int i = t; i < HH * HH; i += 256) sW2[i] = NW2[i];
    for (int i = t; i < HH; i += 256) { sB1[i] = NB1[i]; sB2[i] = NB2[i]; }
    __syncthreads();

    const int nL = t >> 2, sub = t & 3, jo = sub * 16;
    const int n = blockIdx.x * NPB + nL;
    const bool valid = (n < NN);
    const int nc = valid ? n : (NN - 1);

    u64 acc[8];
    load16(acc, sB1 + jo);
    {
        const float4* hv = (const float4*)(h_in + (size_t)nc * HH);
#pragma unroll
        for (int q = 0; q < 16; q++) {
            float4 v = hv[q];
            fma16(acc, pack2(v.x), sW1 + (4 * q + 0) * HH + jo);
            fma16(acc, pack2(v.y), sW1 + (4 * q + 1) * HH + jo);
            fma16(acc, pack2(v.z), sW1 + (4 * q + 2) * HH + jo);
            fma16(acc, pack2(v.w), sW1 + (4 * q + 3) * HH + jo);
        }
        const float4* mv = (const float4*)(g_aggmsg + (size_t)nc * HH);
#pragma unroll
        for (int q = 0; q < 16; q++) {
            float4 v = mv[q];
            fma16(acc, pack2(v.x), sW1 + (HH + 4 * q + 0) * HH + jo);
            fma16(acc, pack2(v.y), sW1 + (HH + 4 * q + 1) * HH + jo);
            fma16(acc, pack2(v.z), sW1 + (HH + 4 * q + 2) * HH + jo);
            fma16(acc, pack2(v.w), sW1 + (HH + 4 * q + 3) * HH + jo);
        }
    }
    {
        float4* myH = (float4*)(stH + nL * 68 + jo);
#pragma unroll
        for (int q = 0; q < 4; q++) {
            float a, b, cc, d;
            unpack2(acc[2 * q], a, b);
            unpack2(acc[2 * q + 1], cc, d);
            myH[q] = make_float4(silu_f(a), silu_f(b), silu_f(cc), silu_f(d));
        }
    }
    __syncwarp();

    load16(acc, sB2 + jo);
    {
        const float4* hs = (const float4*)(stH + nL * 68);
#pragma unroll
        for (int q = 0; q < 16; q++) {
            float4 v = hs[q];
            fma16(acc, pack2(v.x), sW2 + (4 * q + 0) * HH + jo);
            fma16(acc, pack2(v.y), sW2 + (4 * q + 1) * HH + jo);
            fma16(acc, pack2(v.z), sW2 + (4 * q + 2) * HH + jo);
            fma16(acc, pack2(v.w), sW2 + (4 * q + 3) * HH + jo);
        }
    }
    if (valid) {
        float4* op = (float4*)(h_out + (size_t)n * HH + jo);
        float4* oh = (float4*)(out_h + (size_t)n * HH + jo);
#pragma unroll
        for (int q = 0; q < 4; q++) {
            float a, b, cc, d;
            unpack2(acc[2 * q], a, b);
            unpack2(acc[2 * q + 1], cc, d);
            float4 o = make_float4(a, b, cc, d);
            op[q] = o;
            if (writeOut) oh[q] = o;
        }
        if (sub == 0) {
            float cnt = g_cnt[n];
            float inv = 1.0f / fmaxf(cnt, 1.0f);
#pragma unroll
            for (int d = 0; d < 3; d++) {
                float tot = g_aggf[n * 3 + d] * inv;
                tot = fminf(fmaxf(tot, -100.0f), 100.0f);
                float nx = g_x[n * 3 + d] + tot;
                g_x[n * 3 + d] = nx;
                if (writeOut) out_x[n * 3 + d] = nx;
            }
        }
    }
}

// ---------------- launch ----------------
extern "C" void kernel_launch(void* const* d_in, const int* in_sizes, int n_in,
                              void* d_out, int out_size) {
    const float* x    = (const float*)d_in[0];
    const float* h    = (const float*)d_in[1];
    const int*   row  = (const int*)d_in[2];
    const int*   col  = (const int*)d_in[3];
    const float* efea = (const float*)d_in[4];
    const float* embW = (const float*)d_in[5];
    const float* embB = (const float*)d_in[6];
    const float* eW1  = (const float*)d_in[7];
    const float* eB1  = (const float*)d_in[8];
    const float* eW2  = (const float*)d_in[9];
    const float* eB2  = (const float*)d_in[10];
    const float* cW1  = (const float*)d_in[11];
    const float* cB1  = (const float*)d_in[12];
    const float* cW2  = (const float*)d_in[13];
    const float* cB2  = (const float*)d_in[14];
    const float* nW1  = (const float*)d_in[15];
    const float* nB1  = (const float*)d_in[16];
    const float* nW2  = (const float*)d_in[17];
    const float* nB2  = (const float*)d_in[18];
    float* out = (float*)d_out;

    void *p_x, *p_h0, *p_h1, *p_am, *p_af, *p_cnt;
    cudaGetSymbolAddress(&p_x, g_x);
    cudaGetSymbolAddress(&p_h0, g_h0);
    cudaGetSymbolAddress(&p_h1, g_h1);
    cudaGetSymbolAddress(&p_am, g_aggmsg);
    cudaGetSymbolAddress(&p_af, g_aggf);
    cudaGetSymbolAddress(&p_cnt, g_cnt);

    const int edge_smem = EDGE_SMEM_FLOATS * sizeof(float);
    const int node_smem = NODE_SMEM_FLOATS * sizeof(float);
    cudaFuncSetAttribute(k_edge, cudaFuncAttributeMaxDynamicSharedMemorySize, edge_smem);
    cudaFuncSetAttribute(k_node, cudaFuncAttributeMaxDynamicSharedMemorySize, node_smem);

    cudaMemcpyAsync(p_x, x, NN * 3 * sizeof(float), cudaMemcpyDeviceToDevice, 0);
    cudaMemsetAsync(p_cnt, 0, NN * sizeof(float), 0);
    k_cnt<<<(MM + 255) / 256, 256>>>(row);
    k_embed<<<(NN * 4 + 255) / 256, 256>>>(h, embW, embB);

    float* hbuf[2] = {(float*)p_h0, (float*)p_h1};
    float* out_x = out;
    float* out_h = out + (size_t)NN * 3;

    for (int i = 0; i < LL; i++) {
        cudaMemsetAsync(p_am, 0, (size_t)NN * HH * sizeof(float), 0);
        cudaMemsetAsync(p_af, 0, (size_t)NN * 3 * sizeof(float), 0);
        k_edge<<<MM / EPB, 256, edge_smem>>>(
            hbuf[i & 1], row, col, efea,
            eW1 + (size_t)i * DIN * HH, eB1 + (size_t)i * HH,
            eW2 + (size_t)i * HH * HH,  eB2 + (size_t)i * HH,
            cW1 + (size_t)i * HH * HH,  cB1 + (size_t)i * HH,
            cW2 + (size_t)i * HH,       cB2 + (size_t)i * 1);
        k_node<<<(NN + NPB - 1) / NPB, 256, node_smem>>>(
            hbuf[i & 1], hbuf[(i + 1) & 1],
            nW1 + (size_t)i * 2 * HH * HH, nB1 + (size_t)i * HH,
            nW2 + (size_t)i * HH * HH,     nB2 + (size_t)i * HH,
            out_x, out_h, (i == LL - 1) ? 1 : 0);
    }
    (void)in_sizes; (void)n_in; (void)out_size;
}

// round 3
// speedup vs baseline: 2.9165x; 2.9165x over previous
#include <cuda_runtime.h>

#define NN 50000
#define MM 800000
#define HH 64
#define EE 8
#define INN 16
#define DIN 137  // 1 + 2*H + E
#define LL 2

typedef unsigned long long u64;

// ---------------- device scratch (no allocs allowed) ----------------
__device__ float g_h0[NN * HH];
__device__ float g_h1[NN * HH];
__device__ float g_x[NN * 3];
__device__ float g_aggmsg[NN * HH];
__device__ float g_aggf[NN * 4];   // padded to 4 for vector atomics
__device__ float g_cnt[NN];

__device__ __forceinline__ float silu_f(float v) {
    return __fdividef(v, 1.0f + __expf(-v));
}

__device__ __forceinline__ u64 pack2(float s) {
    u64 r;
    asm("mov.b64 %0, {%1, %1};" : "=l"(r) : "f"(s));
    return r;
}
__device__ __forceinline__ void unpack2(u64 v, float& lo, float& hi) {
    asm("mov.b64 {%0, %1}, %2;" : "=f"(lo), "=f"(hi) : "l"(v));
}
__device__ __forceinline__ void fma2(u64& acc, u64 w, u64 s) {
    asm("fma.rn.f32x2 %0, %1, %2, %0;" : "+l"(acc) : "l"(w), "l"(s));
}
// vector atomic add (no return) — 4 floats, 16B-aligned address
__device__ __forceinline__ void red4(float* p, float a, float b, float c, float d) {
    asm volatile("red.global.add.v4.f32 [%0], {%1, %2, %3, %4};"
                 :: "l"(p), "f"(a), "f"(b), "f"(c), "f"(d) : "memory");
}

// acc: 64 outputs as 32 f32x2. w: 64-float weight row in shared (broadcast).
__device__ __forceinline__ void fmaB(u64* acc, u64 s2, const float* w) {
    const ulonglong2* w2 = reinterpret_cast<const ulonglong2*>(w);
#pragma unroll
    for (int q = 0; q < 16; q++) {
        ulonglong2 t = w2[q];
        fma2(acc[2 * q],     t.x, s2);
        fma2(acc[2 * q + 1], t.y, s2);
    }
}
__device__ __forceinline__ void loadB(u64* acc, const float* b) {
    const ulonglong2* p = reinterpret_cast<const ulonglong2*>(b);
#pragma unroll
    for (int q = 0; q < 16; q++) {
        ulonglong2 v = p[q];
        acc[2 * q] = v.x;
        acc[2 * q + 1] = v.y;
    }
}
__device__ __forceinline__ void unpack_silu(const u64* acc, float* f) {
#pragma unroll
    for (int q = 0; q < 32; q++) {
        float a, b;
        unpack2(acc[q], a, b);
        f[2 * q]     = silu_f(a);
        f[2 * q + 1] = silu_f(b);
    }
}

// ---------------- embedding: h0 = h @ embW + embB ----------------
__global__ __launch_bounds__(128) void k_embed(const float* __restrict__ h_in,
                                               const float* __restrict__ W,
                                               const float* __restrict__ b) {
    __shared__ float sW[INN * HH];
    __shared__ float sb[HH];
    for (int i = threadIdx.x; i < INN * HH; i += blockDim.x) sW[i] = W[i];
    for (int i = threadIdx.x; i < HH; i += blockDim.x) sb[i] = b[i];
    __syncthreads();
    int n = blockIdx.x * blockDim.x + threadIdx.x;
    if (n >= NN) return;
    u64 acc[32];
    loadB(acc, sb);
    const float4* hv = (const float4*)(h_in + (size_t)n * INN);
#pragma unroll
    for (int q = 0; q < INN / 4; q++) {
        float4 v = hv[q];
        fmaB(acc, pack2(v.x), sW + (4 * q + 0) * HH);
        fmaB(acc, pack2(v.y), sW + (4 * q + 1) * HH);
        fmaB(acc, pack2(v.z), sW + (4 * q + 2) * HH);
        fmaB(acc, pack2(v.w), sW + (4 * q + 3) * HH);
    }
    ulonglong2* outp = (ulonglong2*)(g_h0 + (size_t)n * HH);
#pragma unroll
    for (int q = 0; q < 16; q++)
        outp[q] = make_ulonglong2(acc[2 * q], acc[2 * q + 1]);
}

// ---------------- degree count ----------------
__global__ void k_cnt(const int* __restrict__ row) {
    int e = blockIdx.x * blockDim.x + threadIdx.x;
    if (e < MM) atomicAdd(&g_cnt[row[e]], 1.0f);
}

// ---------------- fused edge kernel (thread per edge, broadcast weights) ---
#define EDGE_SMEM_FLOATS (DIN * HH + 2 * HH * HH + 4 * HH + 4)

__global__ __launch_bounds__(128, 3) void k_edge(
    const float* __restrict__ h_in,
    const int* __restrict__ row, const int* __restrict__ col,
    const float* __restrict__ efea,
    const float* __restrict__ W1, const float* __restrict__ B1,
    const float* __restrict__ W2, const float* __restrict__ B2,
    const float* __restrict__ CW1, const float* __restrict__ CB1,
    const float* __restrict__ CW2, const float* __restrict__ CB2) {
    extern __shared__ float sm[];
    float* sW1  = sm;                 // [137][64] k-major
    float* sW2  = sW1 + DIN * HH;     // [64][64] k-major
    float* sCW1 = sW2 + HH * HH;      // [64][64] k-major
    float* sB1  = sCW1 + HH * HH;
    float* sB2  = sB1 + HH;
    float* sCB1 = sB2 + HH;
    float* sCW2 = sCB1 + HH;
    float* sCB2 = sCW2 + HH;          // 1 + 3 pad

    const int t = threadIdx.x;
    for (int i = t; i < DIN * HH; i += 128) sW1[i] = W1[i];
    for (int i = t; i < HH * HH; i += 128) { sW2[i] = W2[i]; sCW1[i] = CW1[i]; }
    for (int i = t; i < HH; i += 128) {
        sB1[i] = B1[i]; sB2[i] = B2[i]; sCB1[i] = CB1[i]; sCW2[i] = CW2[i];
    }
    if (t == 0) sCB2[0] = CB2[0];
    __syncthreads();

    const int e = blockIdx.x * 128 + t;   // MM % 128 == 0
    const int r = row[e], c = col[e];
    const float rx = g_x[r * 3 + 0] - g_x[c * 3 + 0];
    const float ry = g_x[r * 3 + 1] - g_x[c * 3 + 1];
    const float rz = g_x[r * 3 + 2] - g_x[c * 3 + 2];
    const float r2 = rx * rx + ry * ry + rz * rz;

    u64 acc[32];

    // ---- stage 1: hid = silu([r2, h[r], h[c], efea] @ W1 + b1) ----
    loadB(acc, sB1);
    fmaB(acc, pack2(r2), sW1);  // k = 0
    {
        const float4* hr = (const float4*)(h_in + (size_t)r * HH);
#pragma unroll
        for (int q = 0; q < 16; q++) {
            float4 v = hr[q];
            fmaB(acc, pack2(v.x), sW1 + (1 + 4 * q + 0) * HH);
            fmaB(acc, pack2(v.y), sW1 + (1 + 4 * q + 1) * HH);
            fmaB(acc, pack2(v.z), sW1 + (1 + 4 * q + 2) * HH);
            fmaB(acc, pack2(v.w), sW1 + (1 + 4 * q + 3) * HH);
        }
        const float4* hc = (const float4*)(h_in + (size_t)c * HH);
#pragma unroll
        for (int q = 0; q < 16; q++) {
            float4 v = hc[q];
            fmaB(acc, pack2(v.x), sW1 + (1 + HH + 4 * q + 0) * HH);
            fmaB(acc, pack2(v.y), sW1 + (1 + HH + 4 * q + 1) * HH);
            fmaB(acc, pack2(v.z), sW1 + (1 + HH + 4 * q + 2) * HH);
            fmaB(acc, pack2(v.w), sW1 + (1 + HH + 4 * q + 3) * HH);
        }
        const float4* ef = (const float4*)(efea + (size_t)e * EE);
#pragma unroll
        for (int q = 0; q < 2; q++) {
            float4 v = ef[q];
            fmaB(acc, pack2(v.x), sW1 + (1 + 2 * HH + 4 * q + 0) * HH);
            fmaB(acc, pack2(v.y), sW1 + (1 + 2 * HH + 4 * q + 1) * HH);
            fmaB(acc, pack2(v.z), sW1 + (1 + 2 * HH + 4 * q + 2) * HH);
            fmaB(acc, pack2(v.w), sW1 + (1 + 2 * HH + 4 * q + 3) * HH);
        }
    }
    float hid[HH];
    unpack_silu(acc, hid);

    // ---- stage 2: msg = silu(hid @ W2 + b2) ----
    loadB(acc, sB2);
#pragma unroll
    for (int k = 0; k < HH; k++) fmaB(acc, pack2(hid[k]), sW2 + k * HH);
    float msg[HH];
    unpack_silu(acc, msg);
    {
        float* am = &g_aggmsg[(size_t)r * HH];
#pragma unroll
        for (int q = 0; q < 16; q++)
            red4(am + 4 * q, msg[4 * q], msg[4 * q + 1], msg[4 * q + 2], msg[4 * q + 3]);
    }

    // ---- stage 3: cm = silu(msg @ CW1 + cb1) . CW2 + cb2 ----
    loadB(acc, sCB1);
#pragma unroll
    for (int k = 0; k < HH; k++) fmaB(acc, pack2(msg[k]), sCW1 + k * HH);
    float cm = sCB2[0];
#pragma unroll
    for (int q = 0; q < 32; q++) {
        float a, b;
        unpack2(acc[q], a, b);
        cm += silu_f(a) * sCW2[2 * q];
        cm += silu_f(b) * sCW2[2 * q + 1];
    }
    red4(&g_aggf[(size_t)r * 4], rx * cm, ry * cm, rz * cm, 0.0f);
}

// ---------------- node kernel: coord update + node MLP ----------------
#define NODE_SMEM_FLOATS (2 * HH * HH + HH * HH + 2 * HH)

__global__ __launch_bounds__(128, 3) void k_node(
    const float* __restrict__ h_in, float* __restrict__ h_out,
    const float* __restrict__ NW1, const float* __restrict__ NB1,
    const float* __restrict__ NW2, const float* __restrict__ NB2,
    float* __restrict__ out_x, float* __restrict__ out_h, int writeOut) {
    extern __shared__ float sm[];
    float* sW1 = sm;                  // [2H][H] k-major
    float* sW2 = sW1 + 2 * HH * HH;   // [H][H] k-major
    float* sB1 = sW2 + HH * HH;
    float* sB2 = sB1 + HH;

    const int t = threadIdx.x;
    for (int i = t; i < 2 * HH * HH; i += 128) sW1[i] = NW1[i];
    for (int i = t; i < HH * HH; i += 128) sW2[i] = NW2[i];
    for (int i = t; i < HH; i += 128) { sB1[i] = NB1[i]; sB2[i] = NB2[i]; }
    __syncthreads();

    const int n = blockIdx.x * 128 + t;
    if (n >= NN) return;

    u64 acc[32];
    loadB(acc, sB1);
    {
        const float4* hv = (const float4*)(h_in + (size_t)n * HH);
#pragma unroll
        for (int q = 0; q < 16; q++) {
            float4 v = hv[q];
            fmaB(acc, pack2(v.x), sW1 + (4 * q + 0) * HH);
            fmaB(acc, pack2(v.y), sW1 + (4 * q + 1) * HH);
            fmaB(acc, pack2(v.z), sW1 + (4 * q + 2) * HH);
            fmaB(acc, pack2(v.w), sW1 + (4 * q + 3) * HH);
        }
        const float4* mv = (const float4*)(g_aggmsg + (size_t)n * HH);
#pragma unroll
        for (int q = 0; q < 16; q++) {
            float4 v = mv[q];
            fmaB(acc, pack2(v.x), sW1 + (HH + 4 * q + 0) * HH);
            fmaB(acc, pack2(v.y), sW1 + (HH + 4 * q + 1) * HH);
            fmaB(acc, pack2(v.z), sW1 + (HH + 4 * q + 2) * HH);
            fmaB(acc, pack2(v.w), sW1 + (HH + 4 * q + 3) * HH);
        }
    }
    float hid[HH];
    unpack_silu(acc, hid);

    loadB(acc, sB2);
#pragma unroll
    for (int k = 0; k < HH; k++) fmaB(acc, pack2(hid[k]), sW2 + k * HH);

    {
        ulonglong2* op = (ulonglong2*)(h_out + (size_t)n * HH);
#pragma unroll
        for (int q = 0; q < 16; q++)
            op[q] = make_ulonglong2(acc[2 * q], acc[2 * q + 1]);
        if (writeOut) {
            ulonglong2* oh = (ulonglong2*)(out_h + (size_t)n * HH);
#pragma unroll
            for (int q = 0; q < 16; q++)
                oh[q] = make_ulonglong2(acc[2 * q], acc[2 * q + 1]);
        }
    }

    // coord update: x += clip(sum_f / max(cnt,1), -100, 100)
    float cnt = g_cnt[n];
    float inv = 1.0f / fmaxf(cnt, 1.0f);
#pragma unroll
    for (int d = 0; d < 3; d++) {
        float tot = g_aggf[(size_t)n * 4 + d] * inv;
        tot = fminf(fmaxf(tot, -100.0f), 100.0f);
        float nx = g_x[n * 3 + d] + tot;
        g_x[n * 3 + d] = nx;
        if (writeOut) out_x[n * 3 + d] = nx;
    }
}

// ---------------- launch ----------------
extern "C" void kernel_launch(void* const* d_in, const int* in_sizes, int n_in,
                              void* d_out, int out_size) {
    const float* x    = (const float*)d_in[0];
    const float* h    = (const float*)d_in[1];
    const int*   row  = (const int*)d_in[2];
    const int*   col  = (const int*)d_in[3];
    const float* efea = (const float*)d_in[4];
    const float* embW = (const float*)d_in[5];
    const float* embB = (const float*)d_in[6];
    const float* eW1  = (const float*)d_in[7];
    const float* eB1  = (const float*)d_in[8];
    const float* eW2  = (const float*)d_in[9];
    const float* eB2  = (const float*)d_in[10];
    const float* cW1  = (const float*)d_in[11];
    const float* cB1  = (const float*)d_in[12];
    const float* cW2  = (const float*)d_in[13];
    const float* cB2  = (const float*)d_in[14];
    const float* nW1  = (const float*)d_in[15];
    const float* nB1  = (const float*)d_in[16];
    const float* nW2  = (const float*)d_in[17];
    const float* nB2  = (const float*)d_in[18];
    float* out = (float*)d_out;

    void *p_x, *p_h0, *p_h1, *p_am, *p_af, *p_cnt;
    cudaGetSymbolAddress(&p_x, g_x);
    cudaGetSymbolAddress(&p_h0, g_h0);
    cudaGetSymbolAddress(&p_h1, g_h1);
    cudaGetSymbolAddress(&p_am, g_aggmsg);
    cudaGetSymbolAddress(&p_af, g_aggf);
    cudaGetSymbolAddress(&p_cnt, g_cnt);

    const int edge_smem = EDGE_SMEM_FLOATS * sizeof(float);
    const int node_smem = NODE_SMEM_FLOATS * sizeof(float);
    cudaFuncSetAttribute(k_edge, cudaFuncAttributeMaxDynamicSharedMemorySize, edge_smem);
    cudaFuncSetAttribute(k_node, cudaFuncAttributeMaxDynamicSharedMemorySize, node_smem);

    cudaMemcpyAsync(p_x, x, NN * 3 * sizeof(float), cudaMemcpyDeviceToDevice, 0);
    cudaMemsetAsync(p_cnt, 0, NN * sizeof(float), 0);
    k_cnt<<<(MM + 255) / 256, 256>>>(row);
    k_embed<<<(NN + 127) / 128, 128>>>(h, embW, embB);

    float* hbuf[2] = {(float*)p_h0, (float*)p_h1};
    float* out_x = out;
    float* out_h = out + (size_t)NN * 3;

    for (int i = 0; i < LL; i++) {
        cudaMemsetAsync(p_am, 0, (size_t)NN * HH * sizeof(float), 0);
        cudaMemsetAsync(p_af, 0, (size_t)NN * 4 * sizeof(float), 0);
        k_edge<<<MM / 128, 128, edge_smem>>>(
            hbuf[i & 1], row, col, efea,
            eW1 + (size_t)i * DIN * HH, eB1 + (size_t)i * HH,
            eW2 + (size_t)i * HH * HH,  eB2 + (size_t)i * HH,
            cW1 + (size_t)i * HH * HH,  cB1 + (size_t)i * HH,
            cW2 + (size_t)i * HH,       cB2 + (size_t)i * 1);
        k_node<<<(NN + 127) / 128, 128, node_smem>>>(
            hbuf[i & 1], hbuf[(i + 1) & 1],
            nW1 + (size_t)i * 2 * HH * HH, nB1 + (size_t)i * HH,
            nW2 + (size_t)i * HH * HH,     nB2 + (size_t)i * HH,
            out_x, out_h, (i == LL - 1) ? 1 : 0);
    }
    (void)in_sizes; (void)n_in; (void)out_size;
}

// round 4
// speedup vs baseline: 4.5001x; 1.5430x over previous
#include <cuda_runtime.h>

#define NN 50000
#define MM 800000
#define HH 64
#define EE 8
#define INN 16
#define DIN 137  // 1 + 2*H + E
#define LL 2

typedef unsigned long long u64;

// ---------------- device scratch (no allocs allowed) ----------------
__device__ float g_h0[NN * HH];
__device__ float g_h1[NN * HH];
__device__ float g_x[NN * 3];
__device__ float g_aggmsg[NN * HH];
__device__ float g_aggf[NN * 4];   // padded to 4 for vector atomics
__device__ float g_cnt[NN];

__device__ __forceinline__ float silu_f(float v) {
    return __fdividef(v, 1.0f + __expf(-v));
}

__device__ __forceinline__ u64 pack2(float s) {
    u64 r;
    asm("mov.b64 %0, {%1, %1};" : "=l"(r) : "f"(s));
    return r;
}
__device__ __forceinline__ void unpack2(u64 v, float& lo, float& hi) {
    asm("mov.b64 {%0, %1}, %2;" : "=f"(lo), "=f"(hi) : "l"(v));
}
__device__ __forceinline__ void fma2(u64& acc, u64 w, u64 s) {
    asm("fma.rn.f32x2 %0, %1, %2, %0;" : "+l"(acc) : "l"(w), "l"(s));
}
__device__ __forceinline__ void red4(float* p, float a, float b, float c, float d) {
    asm volatile("red.global.add.v4.f32 [%0], {%1, %2, %3, %4};"
                 :: "l"(p), "f"(a), "f"(b), "f"(c), "f"(d) : "memory");
}

// interleaved position of output j within a 64-float weight row:
// chunk m = 2*((j&31)>>2) + (j>>5), offset j&3
__host__ __device__ __forceinline__ int PERM(int j) {
    return (((j & 31) >> 2) << 3) + ((j >> 5) << 2) + (j & 3);
}

// one k-step for BOTH edges of a pair: 8 LDS.128 + 32 FMA2
// wh = weight row base + 4*h floats (h = half)
__device__ __forceinline__ void fmaPair(u64* a0, u64* a1, u64 s0, u64 s1,
                                        const float* wh) {
#pragma unroll
    for (int c = 0; c < 8; c++) {
        ulonglong2 t = *reinterpret_cast<const ulonglong2*>(wh + (c << 3));
        fma2(a0[2 * c],     t.x, s0);
        fma2(a0[2 * c + 1], t.y, s0);
        fma2(a1[2 * c],     t.x, s1);
        fma2(a1[2 * c + 1], t.y, s1);
    }
}

// load 16 u64 (32 contiguous floats) from plain array at float offset 32*h
__device__ __forceinline__ void loadHalf(u64* a, const float* b, int h) {
    const ulonglong2* p = reinterpret_cast<const ulonglong2*>(b + (h << 5));
#pragma unroll
    for (int c = 0; c < 8; c++) {
        ulonglong2 v = p[c];
        a[2 * c] = v.x;
        a[2 * c + 1] = v.y;
    }
}

__device__ __forceinline__ void siluHalf(const u64* a, float* f) {
#pragma unroll
    for (int q = 0; q < 16; q++) {
        float x, y;
        unpack2(a[q], x, y);
        f[2 * q]     = silu_f(x);
        f[2 * q + 1] = silu_f(y);
    }
}

// ---------------- embedding (R3 style, full 64 outputs per thread) --------
__device__ __forceinline__ void fmaB(u64* acc, u64 s2, const float* w) {
    const ulonglong2* w2 = reinterpret_cast<const ulonglong2*>(w);
#pragma unroll
    for (int q = 0; q < 16; q++) {
        ulonglong2 t = w2[q];
        fma2(acc[2 * q],     t.x, s2);
        fma2(acc[2 * q + 1], t.y, s2);
    }
}
__device__ __forceinline__ void loadB(u64* acc, const float* b) {
    const ulonglong2* p = reinterpret_cast<const ulonglong2*>(b);
#pragma unroll
    for (int q = 0; q < 16; q++) {
        ulonglong2 v = p[q];
        acc[2 * q] = v.x;
        acc[2 * q + 1] = v.y;
    }
}

__global__ __launch_bounds__(128) void k_embed(const float* __restrict__ h_in,
                                               const float* __restrict__ W,
                                               const float* __restrict__ b) {
    __shared__ float sW[INN * HH];
    __shared__ float sb[HH];
    for (int i = threadIdx.x; i < INN * HH; i += blockDim.x) sW[i] = W[i];
    for (int i = threadIdx.x; i < HH; i += blockDim.x) sb[i] = b[i];
    __syncthreads();
    int n = blockIdx.x * blockDim.x + threadIdx.x;
    if (n >= NN) return;
    u64 acc[32];
    loadB(acc, sb);
    const float4* hv = (const float4*)(h_in + (size_t)n * INN);
#pragma unroll
    for (int q = 0; q < INN / 4; q++) {
        float4 v = hv[q];
        fmaB(acc, pack2(v.x), sW + (4 * q + 0) * HH);
        fmaB(acc, pack2(v.y), sW + (4 * q + 1) * HH);
        fmaB(acc, pack2(v.z), sW + (4 * q + 2) * HH);
        fmaB(acc, pack2(v.w), sW + (4 * q + 3) * HH);
    }
    ulonglong2* outp = (ulonglong2*)(g_h0 + (size_t)n * HH);
#pragma unroll
    for (int q = 0; q < 16; q++)
        outp[q] = make_ulonglong2(acc[2 * q], acc[2 * q + 1]);
}

// ---------------- degree count ----------------
__global__ void k_cnt(const int* __restrict__ row) {
    int e = blockIdx.x * blockDim.x + threadIdx.x;
    if (e < MM) atomicAdd(&g_cnt[row[e]], 1.0f);
}

// ---------------- fused edge kernel: pair-split, 2 edges per thread ------
#define EDGE_SMEM_FLOATS (DIN * HH + 2 * HH * HH + 4 * HH + 4)

__global__ __launch_bounds__(128, 3) void k_edge(
    const float* __restrict__ h_in,
    const int* __restrict__ row, const int* __restrict__ col,
    const float* __restrict__ efea,
    const float* __restrict__ W1, const float* __restrict__ B1,
    const float* __restrict__ W2, const float* __restrict__ B2,
    const float* __restrict__ CW1, const float* __restrict__ CB1,
    const float* __restrict__ CW2, const float* __restrict__ CB2) {
    extern __shared__ float sm[];
    float* sW1  = sm;                 // [137][64] interleaved
    float* sW2  = sW1 + DIN * HH;     // [64][64] interleaved
    float* sCW1 = sW2 + HH * HH;      // [64][64] interleaved
    float* sB1  = sCW1 + HH * HH;     // plain
    float* sB2  = sB1 + HH;
    float* sCB1 = sB2 + HH;
    float* sCW2 = sCB1 + HH;
    float* sCB2 = sCW2 + HH;

    const int t = threadIdx.x;
    for (int i = t; i < DIN * HH; i += 128) {
        int k = i >> 6, j = i & 63;
        sW1[(k << 6) + PERM(j)] = W1[i];
    }
    for (int i = t; i < HH * HH; i += 128) {
        int k = i >> 6, j = i & 63;
        int p = (k << 6) + PERM(j);
        sW2[p] = W2[i];
        sCW1[p] = CW1[i];
    }
    for (int i = t; i < HH; i += 128) {
        sB1[i] = B1[i]; sB2[i] = B2[i]; sCB1[i] = CB1[i]; sCW2[i] = CW2[i];
    }
    if (t == 0) sCB2[0] = CB2[0];
    __syncthreads();

    const int lane = t & 31;
    const int h = lane & 1;
    // pair p = lane>>1 owns edges e0=2p, e1=2p+1 within this warp's 32 edges
    const int e0 = blockIdx.x * 128 + (t >> 5) * 32 + ((lane >> 1) << 1);
    const int e1 = e0 + 1;   // MM % 128 == 0, always valid
    const int r0 = row[e0], c0 = col[e0];
    const int r1 = row[e1], c1 = col[e1];
    const float rx0 = g_x[r0 * 3 + 0] - g_x[c0 * 3 + 0];
    const float ry0 = g_x[r0 * 3 + 1] - g_x[c0 * 3 + 1];
    const float rz0 = g_x[r0 * 3 + 2] - g_x[c0 * 3 + 2];
    const float rx1 = g_x[r1 * 3 + 0] - g_x[c1 * 3 + 0];
    const float ry1 = g_x[r1 * 3 + 1] - g_x[c1 * 3 + 1];
    const float rz1 = g_x[r1 * 3 + 2] - g_x[c1 * 3 + 2];
    const float r2_0 = rx0 * rx0 + ry0 * ry0 + rz0 * rz0;
    const float r2_1 = rx1 * rx1 + ry1 * ry1 + rz1 * rz1;

    const int h4 = h << 2;
    u64 a0[16], a1[16];

    // ---- stage 1: hid = silu([r2, h[r], h[c], efea] @ W1 + b1) ----
    loadHalf(a0, sB1, h);
#pragma unroll
    for (int q = 0; q < 16; q++) a1[q] = a0[q];
    fmaPair(a0, a1, pack2(r2_0), pack2(r2_1), sW1 + h4);
    {
        const float4* hr0 = (const float4*)(h_in + (size_t)r0 * HH);
        const float4* hr1 = (const float4*)(h_in + (size_t)r1 * HH);
#pragma unroll
        for (int q = 0; q < 16; q++) {
            float4 u = hr0[q], v = hr1[q];
            fmaPair(a0, a1, pack2(u.x), pack2(v.x), sW1 + ((1 + 4 * q + 0) << 6) + h4);
            fmaPair(a0, a1, pack2(u.y), pack2(v.y), sW1 + ((1 + 4 * q + 1) << 6) + h4);
            fmaPair(a0, a1, pack2(u.z), pack2(v.z), sW1 + ((1 + 4 * q + 2) << 6) + h4);
            fmaPair(a0, a1, pack2(u.w), pack2(v.w), sW1 + ((1 + 4 * q + 3) << 6) + h4);
        }
        const float4* hc0 = (const float4*)(h_in + (size_t)c0 * HH);
        const float4* hc1 = (const float4*)(h_in + (size_t)c1 * HH);
#pragma unroll
        for (int q = 0; q < 16; q++) {
            float4 u = hc0[q], v = hc1[q];
            fmaPair(a0, a1, pack2(u.x), pack2(v.x), sW1 + ((1 + HH + 4 * q + 0) << 6) + h4);
            fmaPair(a0, a1, pack2(u.y), pack2(v.y), sW1 + ((1 + HH + 4 * q + 1) << 6) + h4);
            fmaPair(a0, a1, pack2(u.z), pack2(v.z), sW1 + ((1 + HH + 4 * q + 2) << 6) + h4);
            fmaPair(a0, a1, pack2(u.w), pack2(v.w), sW1 + ((1 + HH + 4 * q + 3) << 6) + h4);
        }
        const float4* ef0 = (const float4*)(efea + (size_t)e0 * EE);
        const float4* ef1 = (const float4*)(efea + (size_t)e1 * EE);
#pragma unroll
        for (int q = 0; q < 2; q++) {
            float4 u = ef0[q], v = ef1[q];
            fmaPair(a0, a1, pack2(u.x), pack2(v.x), sW1 + ((1 + 2 * HH + 4 * q + 0) << 6) + h4);
            fmaPair(a0, a1, pack2(u.y), pack2(v.y), sW1 + ((1 + 2 * HH + 4 * q + 1) << 6) + h4);
            fmaPair(a0, a1, pack2(u.z), pack2(v.z), sW1 + ((1 + 2 * HH + 4 * q + 2) << 6) + h4);
            fmaPair(a0, a1, pack2(u.w), pack2(v.w), sW1 + ((1 + 2 * HH + 4 * q + 3) << 6) + h4);
        }
    }
    float hid0[32], hid1[32];
    siluHalf(a0, hid0);
    siluHalf(a1, hid1);

    // ---- stage 2: msg = silu(hid @ W2 + b2) ----
    loadHalf(a0, sB2, h);
#pragma unroll
    for (int q = 0; q < 16; q++) a1[q] = a0[q];
#pragma unroll
    for (int k = 0; k < HH; k++) {
        const int src = (lane & ~1) | (k >> 5);
        float s0 = __shfl_sync(0xffffffffu, hid0[k & 31], src);
        float s1 = __shfl_sync(0xffffffffu, hid1[k & 31], src);
        fmaPair(a0, a1, pack2(s0), pack2(s1), sW2 + (k << 6) + h4);
    }
    float msg0[32], msg1[32];
    siluHalf(a0, msg0);
    siluHalf(a1, msg1);
    {
        float* am0 = &g_aggmsg[(size_t)r0 * HH + (h << 5)];
        float* am1 = &g_aggmsg[(size_t)r1 * HH + (h << 5)];
#pragma unroll
        for (int c = 0; c < 8; c++)
            red4(am0 + 4 * c, msg0[4 * c], msg0[4 * c + 1], msg0[4 * c + 2], msg0[4 * c + 3]);
#pragma unroll
        for (int c = 0; c < 8; c++)
            red4(am1 + 4 * c, msg1[4 * c], msg1[4 * c + 1], msg1[4 * c + 2], msg1[4 * c + 3]);
    }

    // ---- stage 3: cm = silu(msg @ CW1 + cb1) . CW2 + cb2 ----
    loadHalf(a0, sCB1, h);
#pragma unroll
    for (int q = 0; q < 16; q++) a1[q] = a0[q];
#pragma unroll
    for (int k = 0; k < HH; k++) {
        const int src = (lane & ~1) | (k >> 5);
        float s0 = __shfl_sync(0xffffffffu, msg0[k & 31], src);
        float s1 = __shfl_sync(0xffffffffu, msg1[k & 31], src);
        fmaPair(a0, a1, pack2(s0), pack2(s1), sCW1 + (k << 6) + h4);
    }
    float cm0 = 0.0f, cm1 = 0.0f;
#pragma unroll
    for (int q = 0; q < 16; q++) {
        float x0, y0, x1, y1;
        unpack2(a0[q], x0, y0);
        unpack2(a1[q], x1, y1);
        const float wA = sCW2[(h << 5) + 2 * q];
        const float wB = sCW2[(h << 5) + 2 * q + 1];
        cm0 += silu_f(x0) * wA + silu_f(y0) * wB;
        cm1 += silu_f(x1) * wA + silu_f(y1) * wB;
    }
    cm0 += __shfl_xor_sync(0xffffffffu, cm0, 1);
    cm1 += __shfl_xor_sync(0xffffffffu, cm1, 1);
    cm0 += sCB2[0];
    cm1 += sCB2[0];
    if (h == 0)
        red4(&g_aggf[(size_t)r0 * 4], rx0 * cm0, ry0 * cm0, rz0 * cm0, 0.0f);
    else
        red4(&g_aggf[(size_t)r1 * 4], rx1 * cm1, ry1 * cm1, rz1 * cm1, 0.0f);
}

// ---------------- node kernel: coord update + node MLP (R3 style) --------
#define NODE_SMEM_FLOATS (2 * HH * HH + HH * HH + 2 * HH)

__global__ __launch_bounds__(128, 3) void k_node(
    const float* __restrict__ h_in, float* __restrict__ h_out,
    const float* __restrict__ NW1, const float* __restrict__ NB1,
    const float* __restrict__ NW2, const float* __restrict__ NB2,
    float* __restrict__ out_x, float* __restrict__ out_h, int writeOut) {
    extern __shared__ float sm[];
    float* sW1 = sm;
    float* sW2 = sW1 + 2 * HH * HH;
    float* sB1 = sW2 + HH * HH;
    float* sB2 = sB1 + HH;

    const int t = threadIdx.x;
    for (int i = t; i < 2 * HH * HH; i += 128) sW1[i] = NW1[i];
    for (int i = t; i < HH * HH; i += 128) sW2[i] = NW2[i];
    for (int i = t; i < HH; i += 128) { sB1[i] = NB1[i]; sB2[i] = NB2[i]; }
    __syncthreads();

    const int n = blockIdx.x * 128 + t;
    if (n >= NN) return;

    u64 acc[32];
    loadB(acc, sB1);
    {
        const float4* hv = (const float4*)(h_in + (size_t)n * HH);
#pragma unroll
        for (int q = 0; q < 16; q++) {
            float4 v = hv[q];
            fmaB(acc, pack2(v.x), sW1 + (4 * q + 0) * HH);
            fmaB(acc, pack2(v.y), sW1 + (4 * q + 1) * HH);
            fmaB(acc, pack2(v.z), sW1 + (4 * q + 2) * HH);
            fmaB(acc, pack2(v.w), sW1 + (4 * q + 3) * HH);
        }
        const float4* mv = (const float4*)(g_aggmsg + (size_t)n * HH);
#pragma unroll
        for (int q = 0; q < 16; q++) {
            float4 v = mv[q];
            fmaB(acc, pack2(v.x), sW1 + (HH + 4 * q + 0) * HH);
            fmaB(acc, pack2(v.y), sW1 + (HH + 4 * q + 1) * HH);
            fmaB(acc, pack2(v.z), sW1 + (HH + 4 * q + 2) * HH);
            fmaB(acc, pack2(v.w), sW1 + (HH + 4 * q + 3) * HH);
        }
    }
    float hid[HH];
#pragma unroll
    for (int q = 0; q < 32; q++) {
        float a, b;
        unpack2(acc[q], a, b);
        hid[2 * q]     = silu_f(a);
        hid[2 * q + 1] = silu_f(b);
    }

    loadB(acc, sB2);
#pragma unroll
    for (int k = 0; k < HH; k++) fmaB(acc, pack2(hid[k]), sW2 + k * HH);

    {
        ulonglong2* op = (ulonglong2*)(h_out + (size_t)n * HH);
#pragma unroll
        for (int q = 0; q < 16; q++)
            op[q] = make_ulonglong2(acc[2 * q], acc[2 * q + 1]);
        if (writeOut) {
            ulonglong2* oh = (ulonglong2*)(out_h + (size_t)n * HH);
#pragma unroll
            for (int q = 0; q < 16; q++)
                oh[q] = make_ulonglong2(acc[2 * q], acc[2 * q + 1]);
        }
    }

    float cnt = g_cnt[n];
    float inv = 1.0f / fmaxf(cnt, 1.0f);
#pragma unroll
    for (int d = 0; d < 3; d++) {
        float tot = g_aggf[(size_t)n * 4 + d] * inv;
        tot = fminf(fmaxf(tot, -100.0f), 100.0f);
        float nx = g_x[n * 3 + d] + tot;
        g_x[n * 3 + d] = nx;
        if (writeOut) out_x[n * 3 + d] = nx;
    }
}

// ---------------- launch ----------------
extern "C" void kernel_launch(void* const* d_in, const int* in_sizes, int n_in,
                              void* d_out, int out_size) {
    const float* x    = (const float*)d_in[0];
    const float* h    = (const float*)d_in[1];
    const int*   row  = (const int*)d_in[2];
    const int*   col  = (const int*)d_in[3];
    const float* efea = (const float*)d_in[4];
    const float* embW = (const float*)d_in[5];
    const float* embB = (const float*)d_in[6];
    const float* eW1  = (const float*)d_in[7];
    const float* eB1  = (const float*)d_in[8];
    const float* eW2  = (const float*)d_in[9];
    const float* eB2  = (const float*)d_in[10];
    const float* cW1  = (const float*)d_in[11];
    const float* cB1  = (const float*)d_in[12];
    const float* cW2  = (const float*)d_in[13];
    const float* cB2  = (const float*)d_in[14];
    const float* nW1  = (const float*)d_in[15];
    const float* nB1  = (const float*)d_in[16];
    const float* nW2  = (const float*)d_in[17];
    const float* nB2  = (const float*)d_in[18];
    float* out = (float*)d_out;

    void *p_x, *p_h0, *p_h1, *p_am, *p_af, *p_cnt;
    cudaGetSymbolAddress(&p_x, g_x);
    cudaGetSymbolAddress(&p_h0, g_h0);
    cudaGetSymbolAddress(&p_h1, g_h1);
    cudaGetSymbolAddress(&p_am, g_aggmsg);
    cudaGetSymbolAddress(&p_af, g_aggf);
    cudaGetSymbolAddress(&p_cnt, g_cnt);

    const int edge_smem = EDGE_SMEM_FLOATS * sizeof(float);
    const int node_smem = NODE_SMEM_FLOATS * sizeof(float);
    cudaFuncSetAttribute(k_edge, cudaFuncAttributeMaxDynamicSharedMemorySize, edge_smem);
    cudaFuncSetAttribute(k_node, cudaFuncAttributeMaxDynamicSharedMemorySize, node_smem);

    cudaMemcpyAsync(p_x, x, NN * 3 * sizeof(float), cudaMemcpyDeviceToDevice, 0);
    cudaMemsetAsync(p_cnt, 0, NN * sizeof(float), 0);
    k_cnt<<<(MM + 255) / 256, 256>>>(row);
    k_embed<<<(NN + 127) / 128, 128>>>(h, embW, embB);

    float* hbuf[2] = {(float*)p_h0, (float*)p_h1};
    float* out_x = out;
    float* out_h = out + (size_t)NN * 3;

    for (int i = 0; i < LL; i++) {
        cudaMemsetAsync(p_am, 0, (size_t)NN * HH * sizeof(float), 0);
        cudaMemsetAsync(p_af, 0, (size_t)NN * 4 * sizeof(float), 0);
        k_edge<<<MM / 128, 128, edge_smem>>>(
            hbuf[i & 1], row, col, efea,
            eW1 + (size_t)i * DIN * HH, eB1 + (size_t)i * HH,
            eW2 + (size_t)i * HH * HH,  eB2 + (size_t)i * HH,
            cW1 + (size_t)i * HH * HH,  cB1 + (size_t)i * HH,
            cW2 + (size_t)i * HH,       cB2 + (size_t)i * 1);
        k_node<<<(NN + 127) / 128, 128, node_smem>>>(
            hbuf[i & 1], hbuf[(i + 1) & 1],
            nW1 + (size_t)i * 2 * HH * HH, nB1 + (size_t)i * HH,
            nW2 + (size_t)i * HH * HH,     nB2 + (size_t)i * HH,
            out_x, out_h, (i == LL - 1) ? 1 : 0);
    }
    (void)in_sizes; (void)n_in; (void)out_size;
}

// round 6
// speedup vs baseline: 4.6148x; 1.0255x over previous
#include <cuda_runtime.h>

#define NN 50000
#define MM 800000
#define HH 64
#define EE 8
#define INN 16
#define DIN 137  // 1 + 2*H + E
#define LL 2

typedef unsigned long long u64;

// ---------------- device scratch (no allocs allowed) ----------------
__device__ float g_h0[NN * HH];
__device__ float g_h1[NN * HH];
__device__ float g_x[NN * 3];
__device__ float g_aggmsg[NN * HH];
__device__ float g_aggf[NN * 4];   // padded to 4 for vector atomics
__device__ float g_cnt[NN];

__device__ __forceinline__ float silu_f(float v) {
    return __fdividef(v, 1.0f + __expf(-v));
}

__device__ __forceinline__ u64 pack2(float s) {
    u64 r;
    asm("mov.b64 %0, {%1, %1};" : "=l"(r) : "f"(s));
    return r;
}
__device__ __forceinline__ void unpack2(u64 v, float& lo, float& hi) {
    asm("mov.b64 {%0, %1}, %2;" : "=f"(lo), "=f"(hi) : "l"(v));
}
__device__ __forceinline__ void fma2(u64& acc, u64 w, u64 s) {
    asm("fma.rn.f32x2 %0, %1, %2, %0;" : "+l"(acc) : "l"(w), "l"(s));
}
__device__ __forceinline__ void red4(float* p, float a, float b, float c, float d) {
    asm volatile("red.global.add.v4.f32 [%0], {%1, %2, %3, %4};"
                 :: "l"(p), "f"(a), "f"(b), "f"(c), "f"(d) : "memory");
}

// pair interleave: j -> (2c+h)*4+o, h=j>>5, c=(j&31)>>2, o=j&3
__host__ __device__ __forceinline__ int PERM(int j) {
    return (((j & 31) >> 2) << 3) + ((j >> 5) << 2) + (j & 3);
}
// quad interleave: j -> (4c+h)*4+o, h=j>>4, c=(j&15)>>2, o=j&3
__host__ __device__ __forceinline__ int PERM4(int j) {
    return (((j & 15) >> 2) << 4) + ((j >> 4) << 2) + (j & 3);
}

// ---- pair helpers (k_node): one k-step for 2 nodes: 8 LDS.128 + 32 FMA2
__device__ __forceinline__ void fmaPair(u64* a0, u64* a1, u64 s0, u64 s1,
                                        const float* wh) {
#pragma unroll
    for (int c = 0; c < 8; c++) {
        ulonglong2 t = *reinterpret_cast<const ulonglong2*>(wh + (c << 3));
        fma2(a0[2 * c],     t.x, s0);
        fma2(a0[2 * c + 1], t.y, s0);
        fma2(a1[2 * c],     t.x, s1);
        fma2(a1[2 * c + 1], t.y, s1);
    }
}
__device__ __forceinline__ void loadHalf(u64* a, const float* b, int h) {
    const ulonglong2* p = reinterpret_cast<const ulonglong2*>(b + (h << 5));
#pragma unroll
    for (int c = 0; c < 8; c++) {
        ulonglong2 v = p[c];
        a[2 * c] = v.x;
        a[2 * c + 1] = v.y;
    }
}
__device__ __forceinline__ void siluHalf(const u64* a, float* f) {
#pragma unroll
    for (int q = 0; q < 16; q++) {
        float x, y;
        unpack2(a[q], x, y);
        f[2 * q]     = silu_f(x);
        f[2 * q + 1] = silu_f(y);
    }
}

// ---- quad helpers (k_edge): one k-step for 4 edges: 4 LDS.128 + 32 FMA2
__device__ __forceinline__ void fmaQuad(u64* a0, u64* a1, u64* a2, u64* a3,
                                        u64 s0, u64 s1, u64 s2, u64 s3,
                                        const float* wh) {
#pragma unroll
    for (int c = 0; c < 4; c++) {
        ulonglong2 t = *reinterpret_cast<const ulonglong2*>(wh + (c << 4));
        fma2(a0[2 * c],     t.x, s0);
        fma2(a0[2 * c + 1], t.y, s0);
        fma2(a1[2 * c],     t.x, s1);
        fma2(a1[2 * c + 1], t.y, s1);
        fma2(a2[2 * c],     t.x, s2);
        fma2(a2[2 * c + 1], t.y, s2);
        fma2(a3[2 * c],     t.x, s3);
        fma2(a3[2 * c + 1], t.y, s3);
    }
}
__device__ __forceinline__ void loadQuarter(u64* a, const float* b, int h) {
    const ulonglong2* p = reinterpret_cast<const ulonglong2*>(b + (h << 4));
#pragma unroll
    for (int c = 0; c < 4; c++) {
        ulonglong2 v = p[c];
        a[2 * c] = v.x;
        a[2 * c + 1] = v.y;
    }
}
__device__ __forceinline__ void siluQuarter(const u64* a, float* f) {
#pragma unroll
    for (int m = 0; m < 8; m++) {
        float x, y;
        unpack2(a[m], x, y);
        f[2 * m]     = silu_f(x);
        f[2 * m + 1] = silu_f(y);
    }
}

// ---------------- embedding (full 64 outputs per thread) --------
__device__ __forceinline__ void fmaB(u64* acc, u64 s2, const float* w) {
    const ulonglong2* w2 = reinterpret_cast<const ulonglong2*>(w);
#pragma unroll
    for (int q = 0; q < 16; q++) {
        ulonglong2 t = w2[q];
        fma2(acc[2 * q],     t.x, s2);
        fma2(acc[2 * q + 1], t.y, s2);
    }
}
__device__ __forceinline__ void loadB(u64* acc, const float* b) {
    const ulonglong2* p = reinterpret_cast<const ulonglong2*>(b);
#pragma unroll
    for (int q = 0; q < 16; q++) {
        ulonglong2 v = p[q];
        acc[2 * q] = v.x;
        acc[2 * q + 1] = v.y;
    }
}

__global__ __launch_bounds__(128) void k_embed(const float* __restrict__ h_in,
                                               const float* __restrict__ W,
                                               const float* __restrict__ b) {
    __shared__ float sW[INN * HH];
    __shared__ float sb[HH];
    for (int i = threadIdx.x; i < INN * HH; i += blockDim.x) sW[i] = W[i];
    for (int i = threadIdx.x; i < HH; i += blockDim.x) sb[i] = b[i];
    __syncthreads();
    int n = blockIdx.x * blockDim.x + threadIdx.x;
    if (n >= NN) return;
    u64 acc[32];
    loadB(acc, sb);
    const float4* hv = (const float4*)(h_in + (size_t)n * INN);
#pragma unroll
    for (int q = 0; q < INN / 4; q++) {
        float4 v = hv[q];
        fmaB(acc, pack2(v.x), sW + (4 * q + 0) * HH);
        fmaB(acc, pack2(v.y), sW + (4 * q + 1) * HH);
        fmaB(acc, pack2(v.z), sW + (4 * q + 2) * HH);
        fmaB(acc, pack2(v.w), sW + (4 * q + 3) * HH);
    }
    ulonglong2* outp = (ulonglong2*)(g_h0 + (size_t)n * HH);
#pragma unroll
    for (int q = 0; q < 16; q++)
        outp[q] = make_ulonglong2(acc[2 * q], acc[2 * q + 1]);
}

// ---------------- degree count ----------------
__global__ void k_cnt(const int* __restrict__ row) {
    int e = blockIdx.x * blockDim.x + threadIdx.x;
    if (e < MM) atomicAdd(&g_cnt[row[e]], 1.0f);
}

// ---------------- fused edge kernel: quad-split, 4 edges per lane-quad ---
#define EDGE_SMEM_FLOATS (DIN * HH + 2 * HH * HH + 4 * HH + 4)

__global__ __launch_bounds__(128, 3) void k_edge(
    const float* __restrict__ h_in,
    const int* __restrict__ row, const int* __restrict__ col,
    const float* __restrict__ efea,
    const float* __restrict__ W1, const float* __restrict__ B1,
    const float* __restrict__ W2, const float* __restrict__ B2,
    const float* __restrict__ CW1, const float* __restrict__ CB1,
    const float* __restrict__ CW2, const float* __restrict__ CB2) {
    extern __shared__ float sm[];
    float* sW1  = sm;                 // [137][64] PERM4-interleaved
    float* sW2  = sW1 + DIN * HH;     // [64][64]
    float* sCW1 = sW2 + HH * HH;      // [64][64]
    float* sB1  = sCW1 + HH * HH;     // plain
    float* sB2  = sB1 + HH;
    float* sCB1 = sB2 + HH;
    float* sCW2 = sCB1 + HH;
    float* sCB2 = sCW2 + HH;

    const int t = threadIdx.x;
    for (int i = t; i < DIN * HH; i += 128) {
        int k = i >> 6, j = i & 63;
        sW1[(k << 6) + PERM4(j)] = W1[i];
    }
    for (int i = t; i < HH * HH; i += 128) {
        int k = i >> 6, j = i & 63;
        int p = (k << 6) + PERM4(j);
        sW2[p] = W2[i];
        sCW1[p] = CW1[i];
    }
    for (int i = t; i < HH; i += 128) {
        sB1[i] = B1[i]; sB2[i] = B2[i]; sCB1[i] = CB1[i]; sCW2[i] = CW2[i];
    }
    if (t == 0) sCB2[0] = CB2[0];
    __syncthreads();

    const int lane = t & 31;
    const int h = lane & 3;          // quarter id
    const int qd = lane >> 2;        // quad id 0..7
    // warp covers 32 edges; quad covers 4 consecutive edges
    const int e0 = blockIdx.x * 128 + ((t >> 5) << 5) + (qd << 2);
    const int4 rv = *(const int4*)(row + e0);
    const int4 cv = *(const int4*)(col + e0);
    const int r0 = rv.x, r1 = rv.y, r2i = rv.z, r3 = rv.w;
    const int c0 = cv.x, c1 = cv.y, c2 = cv.z, c3 = cv.w;

    const float rx0 = g_x[r0 * 3 + 0] - g_x[c0 * 3 + 0];
    const float ry0 = g_x[r0 * 3 + 1] - g_x[c0 * 3 + 1];
    const float rz0 = g_x[r0 * 3 + 2] - g_x[c0 * 3 + 2];
    const float rx1 = g_x[r1 * 3 + 0] - g_x[c1 * 3 + 0];
    const float ry1 = g_x[r1 * 3 + 1] - g_x[c1 * 3 + 1];
    const float rz1 = g_x[r1 * 3 + 2] - g_x[c1 * 3 + 2];
    const float rx2 = g_x[r2i * 3 + 0] - g_x[c2 * 3 + 0];
    const float ry2 = g_x[r2i * 3 + 1] - g_x[c2 * 3 + 1];
    const float rz2 = g_x[r2i * 3 + 2] - g_x[c2 * 3 + 2];
    const float rx3 = g_x[r3 * 3 + 0] - g_x[c3 * 3 + 0];
    const float ry3 = g_x[r3 * 3 + 1] - g_x[c3 * 3 + 1];
    const float rz3 = g_x[r3 * 3 + 2] - g_x[c3 * 3 + 2];
    const float s2_0 = rx0 * rx0 + ry0 * ry0 + rz0 * rz0;
    const float s2_1 = rx1 * rx1 + ry1 * ry1 + rz1 * rz1;
    const float s2_2 = rx2 * rx2 + ry2 * ry2 + rz2 * rz2;
    const float s2_3 = rx3 * rx3 + ry3 * ry3 + rz3 * rz3;

    const int h4 = h << 2;
    u64 a0[8], a1[8], a2[8], a3[8];

    // ---- stage 1: hid = silu([r2, h[r], h[c], efea] @ W1 + b1) ----
    loadQuarter(a0, sB1, h);
#pragma unroll
    for (int m = 0; m < 8; m++) { a1[m] = a0[m]; a2[m] = a0[m]; a3[m] = a0[m]; }
    fmaQuad(a0, a1, a2, a3, pack2(s2_0), pack2(s2_1), pack2(s2_2), pack2(s2_3),
            sW1 + h4);
    {
        const float4* hr0 = (const float4*)(h_in + (size_t)r0 * HH);
        const float4* hr1 = (const float4*)(h_in + (size_t)r1 * HH);
        const float4* hr2 = (const float4*)(h_in + (size_t)r2i * HH);
        const float4* hr3 = (const float4*)(h_in + (size_t)r3 * HH);
#pragma unroll
        for (int q = 0; q < 16; q++) {
            float4 u0 = hr0[q], u1 = hr1[q], u2 = hr2[q], u3 = hr3[q];
            fmaQuad(a0, a1, a2, a3, pack2(u0.x), pack2(u1.x), pack2(u2.x), pack2(u3.x),
                    sW1 + ((1 + 4 * q + 0) << 6) + h4);
            fmaQuad(a0, a1, a2, a3, pack2(u0.y), pack2(u1.y), pack2(u2.y), pack2(u3.y),
                    sW1 + ((1 + 4 * q + 1) << 6) + h4);
            fmaQuad(a0, a1, a2, a3, pack2(u0.z), pack2(u1.z), pack2(u2.z), pack2(u3.z),
                    sW1 + ((1 + 4 * q + 2) << 6) + h4);
            fmaQuad(a0, a1, a2, a3, pack2(u0.w), pack2(u1.w), pack2(u2.w), pack2(u3.w),
                    sW1 + ((1 + 4 * q + 3) << 6) + h4);
        }
        const float4* hc0 = (const float4*)(h_in + (size_t)c0 * HH);
        const float4* hc1 = (const float4*)(h_in + (size_t)c1 * HH);
        const float4* hc2 = (const float4*)(h_in + (size_t)c2 * HH);
        const float4* hc3 = (const float4*)(h_in + (size_t)c3 * HH);
#pragma unroll
        for (int q = 0; q < 16; q++) {
            float4 u0 = hc0[q], u1 = hc1[q], u2 = hc2[q], u3 = hc3[q];
            fmaQuad(a0, a1, a2, a3, pack2(u0.x), pack2(u1.x), pack2(u2.x), pack2(u3.x),
                    sW1 + ((1 + HH + 4 * q + 0) << 6) + h4);
            fmaQuad(a0, a1, a2, a3, pack2(u0.y), pack2(u1.y), pack2(u2.y), pack2(u3.y),
                    sW1 + ((1 + HH + 4 * q + 1) << 6) + h4);
            fmaQuad(a0, a1, a2, a3, pack2(u0.z), pack2(u1.z), pack2(u2.z), pack2(u3.z),
                    sW1 + ((1 + HH + 4 * q + 2) << 6) + h4);
            fmaQuad(a0, a1, a2, a3, pack2(u0.w), pack2(u1.w), pack2(u2.w), pack2(u3.w),
                    sW1 + ((1 + HH + 4 * q + 3) << 6) + h4);
        }
        const float4* ef0 = (const float4*)(efea + (size_t)e0 * EE);
        const float4* ef1 = (const float4*)(efea + (size_t)(e0 + 1) * EE);
        const float4* ef2 = (const float4*)(efea + (size_t)(e0 + 2) * EE);
        const float4* ef3 = (const float4*)(efea + (size_t)(e0 + 3) * EE);
#pragma unroll
        for (int q = 0; q < 2; q++) {
            float4 u0 = ef0[q], u1 = ef1[q], u2 = ef2[q], u3 = ef3[q];
            fmaQuad(a0, a1, a2, a3, pack2(u0.x), pack2(u1.x), pack2(u2.x), pack2(u3.x),
                    sW1 + ((1 + 2 * HH + 4 * q + 0) << 6) + h4);
            fmaQuad(a0, a1, a2, a3, pack2(u0.y), pack2(u1.y), pack2(u2.y), pack2(u3.y),
                    sW1 + ((1 + 2 * HH + 4 * q + 1) << 6) + h4);
            fmaQuad(a0, a1, a2, a3, pack2(u0.z), pack2(u1.z), pack2(u2.z), pack2(u3.z),
                    sW1 + ((1 + 2 * HH + 4 * q + 2) << 6) + h4);
            fmaQuad(a0, a1, a2, a3, pack2(u0.w), pack2(u1.w), pack2(u2.w), pack2(u3.w),
                    sW1 + ((1 + 2 * HH + 4 * q + 3) << 6) + h4);
        }
    }
    float hid0[16], hid1[16], hid2[16], hid3[16];
    siluQuarter(a0, hid0);
    siluQuarter(a1, hid1);
    siluQuarter(a2, hid2);
    siluQuarter(a3, hid3);

    // ---- stage 2: msg = silu(hid @ W2 + b2) ----
    loadQuarter(a0, sB2, h);
#pragma unroll
    for (int m = 0; m < 8; m++) { a1[m] = a0[m]; a2[m] = a0[m]; a3[m] = a0[m]; }
#pragma unroll
    for (int k = 0; k < HH; k++) {
        const int src = (lane & ~3) | (k >> 4);
        float s0 = __shfl_sync(0xffffffffu, hid0[k & 15], src);
        float s1 = __shfl_sync(0xffffffffu, hid1[k & 15], src);
        float s2 = __shfl_sync(0xffffffffu, hid2[k & 15], src);
        float s3 = __shfl_sync(0xffffffffu, hid3[k & 15], src);
        fmaQuad(a0, a1, a2, a3, pack2(s0), pack2(s1), pack2(s2), pack2(s3),
                sW2 + (k << 6) + h4);
    }
    float msg0[16], msg1[16], msg2[16], msg3[16];
    siluQuarter(a0, msg0);
    siluQuarter(a1, msg1);
    siluQuarter(a2, msg2);
    siluQuarter(a3, msg3);
    {
        const int jo = h << 4;
        float* am0 = &g_aggmsg[(size_t)r0 * HH + jo];
        float* am1 = &g_aggmsg[(size_t)r1 * HH + jo];
        float* am2 = &g_aggmsg[(size_t)r2i * HH + jo];
        float* am3 = &g_aggmsg[(size_t)r3 * HH + jo];
#pragma unroll
        for (int c = 0; c < 4; c++) {
            red4(am0 + 4 * c, msg0[4 * c], msg0[4 * c + 1], msg0[4 * c + 2], msg0[4 * c + 3]);
            red4(am1 + 4 * c, msg1[4 * c], msg1[4 * c + 1], msg1[4 * c + 2], msg1[4 * c + 3]);
            red4(am2 + 4 * c, msg2[4 * c], msg2[4 * c + 1], msg2[4 * c + 2], msg2[4 * c + 3]);
            red4(am3 + 4 * c, msg3[4 * c], msg3[4 * c + 1], msg3[4 * c + 2], msg3[4 * c + 3]);
        }
    }

    // ---- stage 3: cm = silu(msg @ CW1 + cb1) . CW2 + cb2 ----
    loadQuarter(a0, sCB1, h);
#pragma unroll
    for (int m = 0; m < 8; m++) { a1[m] = a0[m]; a2[m] = a0[m]; a3[m] = a0[m]; }
#pragma unroll
    for (int k = 0; k < HH; k++) {
        const int src = (lane & ~3) | (k >> 4);
        float s0 = __shfl_sync(0xffffffffu, msg0[k & 15], src);
        float s1 = __shfl_sync(0xffffffffu, msg1[k & 15], src);
        float s2 = __shfl_sync(0xffffffffu, msg2[k & 15], src);
        float s3 = __shfl_sync(0xffffffffu, msg3[k & 15], src);
        fmaQuad(a0, a1, a2, a3, pack2(s0), pack2(s1), pack2(s2), pack2(s3),
                sCW1 + (k << 6) + h4);
    }
    float cm0 = 0.0f, cm1 = 0.0f, cm2 = 0.0f, cm3 = 0.0f;
#pragma unroll
    for (int m = 0; m < 8; m++) {
        const int j = (h << 4) + 2 * m;
        const float wA = sCW2[j], wB = sCW2[j + 1];
        float x, y;
        unpack2(a0[m], x, y); cm0 += silu_f(x) * wA + silu_f(y) * wB;
        unpack2(a1[m], x, y); cm1 += silu_f(x) * wA + silu_f(y) * wB;
        unpack2(a2[m], x, y); cm2 += silu_f(x) * wA + silu_f(y) * wB;
        unpack2(a3[m], x, y); cm3 += silu_f(x) * wA + silu_f(y) * wB;
    }
    cm0 += __shfl_xor_sync(0xffffffffu, cm0, 1);
    cm0 += __shfl_xor_sync(0xffffffffu, cm0, 2);
    cm1 += __shfl_xor_sync(0xffffffffu, cm1, 1);
    cm1 += __shfl_xor_sync(0xffffffffu, cm1, 2);
    cm2 += __shfl_xor_sync(0xffffffffu, cm2, 1);
    cm2 += __shfl_xor_sync(0xffffffffu, cm2, 2);
    cm3 += __shfl_xor_sync(0xffffffffu, cm3, 1);
    cm3 += __shfl_xor_sync(0xffffffffu, cm3, 2);
    const float cb2v = sCB2[0];
    float fx, fy, fz;
    int re;
    if (h == 0)      { float c = cm0 + cb2v; fx = rx0 * c; fy = ry0 * c; fz = rz0 * c; re = r0; }
    else if (h == 1) { float c = cm1 + cb2v; fx = rx1 * c; fy = ry1 * c; fz = rz1 * c; re = r1; }
    else if (h == 2) { float c = cm2 + cb2v; fx = rx2 * c; fy = ry2 * c; fz = rz2 * c; re = r2i; }
    else             { float c = cm3 + cb2v; fx = rx3 * c; fy = ry3 * c; fz = rz3 * c; re = r3; }
    red4(&g_aggf[(size_t)re * 4], fx, fy, fz, 0.0f);
}

// ---------------- node kernel: pair-split, 2 nodes per lane-pair ---------
#define NODE_SMEM_FLOATS (2 * HH * HH + HH * HH + 2 * HH)

__global__ __launch_bounds__(128, 3) void k_node(
    const float* __restrict__ h_in, float* __restrict__ h_out,
    const float* __restrict__ NW1, const float* __restrict__ NB1,
    const float* __restrict__ NW2, const float* __restrict__ NB2,
    float* __restrict__ out_x, float* __restrict__ out_h, int writeOut) {
    extern __shared__ float sm[];
    float* sW1 = sm;                  // [128][64] PERM-interleaved
    float* sW2 = sW1 + 2 * HH * HH;   // [64][64]
    float* sB1 = sW2 + HH * HH;
    float* sB2 = sB1 + HH;

    const int t = threadIdx.x;
    for (int i = t; i < 2 * HH * HH; i += 128) {
        int k = i >> 6, j = i & 63;
        sW1[(k << 6) + PERM(j)] = NW1[i];
    }
    for (int i = t; i < HH * HH; i += 128) {
        int k = i >> 6, j = i & 63;
        sW2[(k << 6) + PERM(j)] = NW2[i];
    }
    for (int i = t; i < HH; i += 128) { sB1[i] = NB1[i]; sB2[i] = NB2[i]; }
    __syncthreads();

    const int lane = t & 31;
    const int h = lane & 1;
    // pair handles nodes n0, n0+1; clamp so no lane exits before shuffles
    int n0 = (blockIdx.x * 64 + ((t >> 5) << 4) + (lane >> 1)) * 2;
    const bool valid = (n0 < NN);
    if (!valid) n0 = NN - 2;
    const int n1 = n0 + 1;
    const int h4 = h << 2;

    u64 a0[16], a1[16];
    loadHalf(a0, sB1, h);
#pragma unroll
    for (int m = 0; m < 16; m++) a1[m] = a0[m];
    {
        const float4* p0 = (const float4*)(h_in + (size_t)n0 * HH);
        const float4* p1 = (const float4*)(h_in + (size_t)n1 * HH);
#pragma unroll
        for (int q = 0; q < 16; q++) {
            float4 u = p0[q], v = p1[q];
            fmaPair(a0, a1, pack2(u.x), pack2(v.x), sW1 + ((4 * q + 0) << 6) + h4);
            fmaPair(a0, a1, pack2(u.y), pack2(v.y), sW1 + ((4 * q + 1) << 6) + h4);
            fmaPair(a0, a1, pack2(u.z), pack2(v.z), sW1 + ((4 * q + 2) << 6) + h4);
            fmaPair(a0, a1, pack2(u.w), pack2(v.w), sW1 + ((4 * q + 3) << 6) + h4);
        }
        const float4* m0 = (const float4*)(g_aggmsg + (size_t)n0 * HH);
        const float4* m1 = (const float4*)(g_aggmsg + (size_t)n1 * HH);
#pragma unroll
        for (int q = 0; q < 16; q++) {
            float4 u = m0[q], v = m1[q];
            fmaPair(a0, a1, pack2(u.x), pack2(v.x), sW1 + ((HH + 4 * q + 0) << 6) + h4);
            fmaPair(a0, a1, pack2(u.y), pack2(v.y), sW1 + ((HH + 4 * q + 1) << 6) + h4);
            fmaPair(a0, a1, pack2(u.z), pack2(v.z), sW1 + ((HH + 4 * q + 2) << 6) + h4);
            fmaPair(a0, a1, pack2(u.w), pack2(v.w), sW1 + ((HH + 4 * q + 3) << 6) + h4);
        }
    }
    float hid0[32], hid1[32];
    siluHalf(a0, hid0);
    siluHalf(a1, hid1);

    loadHalf(a0, sB2, h);
#pragma unroll
    for (int m = 0; m < 16; m++) a1[m] = a0[m];
#pragma unroll
    for (int k = 0; k < HH; k++) {
        const int src = (lane & ~1) | (k >> 5);
        float s0 = __shfl_sync(0xffffffffu, hid0[k & 31], src);
        float s1 = __shfl_sync(0xffffffffu, hid1[k & 31], src);
        fmaPair(a0, a1, pack2(s0), pack2(s1), sW2 + (k << 6) + h4);
    }

    if (valid) {
        const int jo = h << 5;
        ulonglong2* o0 = (ulonglong2*)(h_out + (size_t)n0 * HH + jo);
        ulonglong2* o1 = (ulonglong2*)(h_out + (size_t)n1 * HH + jo);
#pragma unroll
        for (int c = 0; c < 8; c++) {
            o0[c] = make_ulonglong2(a0[2 * c], a0[2 * c + 1]);
            o1[c] = make_ulonglong2(a1[2 * c], a1[2 * c + 1]);
        }
        if (writeOut) {
            ulonglong2* q0 = (ulonglong2*)(out_h + (size_t)n0 * HH + jo);
            ulonglong2* q1 = (ulonglong2*)(out_h + (size_t)n1 * HH + jo);
#pragma unroll
            for (int c = 0; c < 8; c++) {
                q0[c] = make_ulonglong2(a0[2 * c], a0[2 * c + 1]);
                q1[c] = make_ulonglong2(a1[2 * c], a1[2 * c + 1]);
            }
        }
        // coord update: lane h handles node n0+h
        const int n = n0 + h;
        float cnt = g_cnt[n];
        float inv = 1.0f / fmaxf(cnt, 1.0f);
#pragma unroll
        for (int d = 0; d < 3; d++) {
            float tot = g_aggf[(size_t)n * 4 + d] * inv;
            tot = fminf(fmaxf(tot, -100.0f), 100.0f);
            float nx = g_x[n * 3 + d] + tot;
            g_x[n * 3 + d] = nx;
            if (writeOut) out_x[n * 3 + d] = nx;
        }
    }
}

// ---------------- launch ----------------
extern "C" void kernel_launch(void* const* d_in, const int* in_sizes, int n_in,
                              void* d_out, int out_size) {
    const float* x    = (const float*)d_in[0];
    const float* h    = (const float*)d_in[1];
    const int*   row  = (const int*)d_in[2];
    const int*   col  = (const int*)d_in[3];
    const float* efea = (const float*)d_in[4];
    const float* embW = (const float*)d_in[5];
    const float* embB = (const float*)d_in[6];
    const float* eW1  = (const float*)d_in[7];
    const float* eB1  = (const float*)d_in[8];
    const float* eW2  = (const float*)d_in[9];
    const float* eB2  = (const float*)d_in[10];
    const float* cW1  = (const float*)d_in[11];
    const float* cB1  = (const float*)d_in[12];
    const float* cW2  = (const float*)d_in[13];
    const float* cB2  = (const float*)d_in[14];
    const float* nW1  = (const float*)d_in[15];
    const float* nB1  = (const float*)d_in[16];
    const float* nW2  = (const float*)d_in[17];
    const float* nB2  = (const float*)d_in[18];
    float* out = (float*)d_out;

    void *p_x, *p_h0, *p_h1, *p_am, *p_af, *p_cnt;
    cudaGetSymbolAddress(&p_x, g_x);
    cudaGetSymbolAddress(&p_h0, g_h0);
    cudaGetSymbolAddress(&p_h1, g_h1);
    cudaGetSymbolAddress(&p_am, g_aggmsg);
    cudaGetSymbolAddress(&p_af, g_aggf);
    cudaGetSymbolAddress(&p_cnt, g_cnt);

    const int edge_smem = EDGE_SMEM_FLOATS * sizeof(float);
    const int node_smem = NODE_SMEM_FLOATS * sizeof(float);
    cudaFuncSetAttribute(k_edge, cudaFuncAttributeMaxDynamicSharedMemorySize, edge_smem);
    cudaFuncSetAttribute(k_node, cudaFuncAttributeMaxDynamicSharedMemorySize, node_smem);

    cudaMemcpyAsync(p_x, x, NN * 3 * sizeof(float), cudaMemcpyDeviceToDevice, 0);
    cudaMemsetAsync(p_cnt, 0, NN * sizeof(float), 0);
    k_cnt<<<(MM + 255) / 256, 256>>>(row);
    k_embed<<<(NN + 127) / 128, 128>>>(h, embW, embB);

    float* hbuf[2] = {(float*)p_h0, (float*)p_h1};
    float* out_x = out;
    float* out_h = out + (size_t)NN * 3;

    // k_node: each block covers 64 node-pairs = 128 nodes
    const int node_grid = (NN / 2 + 63) / 64;   // 391

    for (int i = 0; i < LL; i++) {
        cudaMemsetAsync(p_am, 0, (size_t)NN * HH * sizeof(float), 0);
        cudaMemsetAsync(p_af, 0, (size_t)NN * 4 * sizeof(float), 0);
        k_edge<<<MM / 128, 128, edge_smem>>>(
            hbuf[i & 1], row, col, efea,
            eW1 + (size_t)i * DIN * HH, eB1 + (size_t)i * HH,
            eW2 + (size_t)i * HH * HH,  eB2 + (size_t)i * HH,
            cW1 + (size_t)i * HH * HH,  cB1 + (size_t)i * HH,
            cW2 + (size_t)i * HH,       cB2 + (size_t)i * 1);
        k_node<<<node_grid, 128, node_smem>>>(
            hbuf[i & 1], hbuf[(i + 1) & 1],
            nW1 + (size_t)i * 2 * HH * HH, nB1 + (size_t)i * HH,
            nW2 + (size_t)i * HH * HH,     nB2 + (size_t)i * HH,
            out_x, out_h, (i == LL - 1) ? 1 : 0);
    }
    (void)in_sizes; (void)n_in; (void)out_size;
}

// round 7
// speedup vs baseline: 6.2523x; 1.3548x over previous
#include <cuda_runtime.h>

#define NN 50000
#define MM 800000
#define HH 64
#define EE 8
#define INN 16
#define DIN 137  // 1 + 2*H + E
#define LL 2

typedef unsigned long long u64;

// ---------------- device scratch (no allocs allowed) ----------------
__device__ float g_h0[NN * HH];
__device__ float g_h1[NN * HH];
__device__ float g_x[NN * 3];
__device__ float g_aggmsg[NN * HH];
__device__ float g_aggf[NN * 4];   // padded to 4 for vector atomics
__device__ float g_cnt[NN];
__device__ float g_A[NN * HH];     // h @ W1[1:65]  + b1   (row-node term)
__device__ float g_B[NN * HH];     // h @ W1[65:129]       (col-node term)

__device__ __forceinline__ float silu_f(float v) {
    return __fdividef(v, 1.0f + __expf(-v));
}

__device__ __forceinline__ u64 pack2(float s) {
    u64 r;
    asm("mov.b64 %0, {%1, %1};" : "=l"(r) : "f"(s));
    return r;
}
__device__ __forceinline__ void unpack2(u64 v, float& lo, float& hi) {
    asm("mov.b64 {%0, %1}, %2;" : "=f"(lo), "=f"(hi) : "l"(v));
}
__device__ __forceinline__ void fma2(u64& acc, u64 w, u64 s) {
    asm("fma.rn.f32x2 %0, %1, %2, %0;" : "+l"(acc) : "l"(w), "l"(s));
}
__device__ __forceinline__ void add2(u64& acc, u64 v) {
    asm("add.rn.f32x2 %0, %1, %0;" : "+l"(acc) : "l"(v));
}
__device__ __forceinline__ void red4(float* p, float a, float b, float c, float d) {
    asm volatile("red.global.add.v4.f32 [%0], {%1, %2, %3, %4};"
                 :: "l"(p), "f"(a), "f"(b), "f"(c), "f"(d) : "memory");
}

// pair interleave: j -> (2c+h)*4+o
__host__ __device__ __forceinline__ int PERM(int j) {
    return (((j & 31) >> 2) << 3) + ((j >> 5) << 2) + (j & 3);
}
// quad interleave: j -> (4c+h)*4+o
__host__ __device__ __forceinline__ int PERM4(int j) {
    return (((j & 15) >> 2) << 4) + ((j >> 4) << 2) + (j & 3);
}

// ---- pair helpers (k_node)
__device__ __forceinline__ void fmaPair(u64* a0, u64* a1, u64 s0, u64 s1,
                                        const float* wh) {
#pragma unroll
    for (int c = 0; c < 8; c++) {
        ulonglong2 t = *reinterpret_cast<const ulonglong2*>(wh + (c << 3));
        fma2(a0[2 * c],     t.x, s0);
        fma2(a0[2 * c + 1], t.y, s0);
        fma2(a1[2 * c],     t.x, s1);
        fma2(a1[2 * c + 1], t.y, s1);
    }
}
__device__ __forceinline__ void loadHalf(u64* a, const float* b, int h) {
    const ulonglong2* p = reinterpret_cast<const ulonglong2*>(b + (h << 5));
#pragma unroll
    for (int c = 0; c < 8; c++) {
        ulonglong2 v = p[c];
        a[2 * c] = v.x;
        a[2 * c + 1] = v.y;
    }
}
__device__ __forceinline__ void siluHalf(const u64* a, float* f) {
#pragma unroll
    for (int q = 0; q < 16; q++) {
        float x, y;
        unpack2(a[q], x, y);
        f[2 * q]     = silu_f(x);
        f[2 * q + 1] = silu_f(y);
    }
}

// ---- quad helpers (k_edge)
__device__ __forceinline__ void fmaQuad(u64* a0, u64* a1, u64* a2, u64* a3,
                                        u64 s0, u64 s1, u64 s2, u64 s3,
                                        const float* wh) {
#pragma unroll
    for (int c = 0; c < 4; c++) {
        ulonglong2 t = *reinterpret_cast<const ulonglong2*>(wh + (c << 4));
        fma2(a0[2 * c],     t.x, s0);
        fma2(a0[2 * c + 1], t.y, s0);
        fma2(a1[2 * c],     t.x, s1);
        fma2(a1[2 * c + 1], t.y, s1);
        fma2(a2[2 * c],     t.x, s2);
        fma2(a2[2 * c + 1], t.y, s2);
        fma2(a3[2 * c],     t.x, s3);
        fma2(a3[2 * c + 1], t.y, s3);
    }
}
__device__ __forceinline__ void loadQuarter(u64* a, const float* b, int h) {
    const ulonglong2* p = reinterpret_cast<const ulonglong2*>(b + (h << 4));
#pragma unroll
    for (int c = 0; c < 4; c++) {
        ulonglong2 v = p[c];
        a[2 * c] = v.x;
        a[2 * c + 1] = v.y;
    }
}
__device__ __forceinline__ void siluQuarter(const u64* a, float* f) {
#pragma unroll
    for (int m = 0; m < 8; m++) {
        float x, y;
        unpack2(a[m], x, y);
        f[2 * m]     = silu_f(x);
        f[2 * m + 1] = silu_f(y);
    }
}
// init quarter accumulator for one edge: A[r][16h..] + B[c][16h..]
__device__ __forceinline__ void initAB(u64* a, int r, int c, int h) {
    const ulonglong2* pa = (const ulonglong2*)(g_A + (size_t)r * HH + (h << 4));
    const ulonglong2* pb = (const ulonglong2*)(g_B + (size_t)c * HH + (h << 4));
#pragma unroll
    for (int q = 0; q < 4; q++) {
        ulonglong2 va = pa[q];
        ulonglong2 vb = pb[q];
        add2(va.x, vb.x);
        add2(va.y, vb.y);
        a[2 * q] = va.x;
        a[2 * q + 1] = va.y;
    }
}

// ---- broadcast helpers (k_embed / k_pre)
__device__ __forceinline__ void fmaB(u64* acc, u64 s2, const float* w) {
    const ulonglong2* w2 = reinterpret_cast<const ulonglong2*>(w);
#pragma unroll
    for (int q = 0; q < 16; q++) {
        ulonglong2 t = w2[q];
        fma2(acc[2 * q],     t.x, s2);
        fma2(acc[2 * q + 1], t.y, s2);
    }
}
__device__ __forceinline__ void loadB(u64* acc, const float* b) {
    const ulonglong2* p = reinterpret_cast<const ulonglong2*>(b);
#pragma unroll
    for (int q = 0; q < 16; q++) {
        ulonglong2 v = p[q];
        acc[2 * q] = v.x;
        acc[2 * q + 1] = v.y;
    }
}
__device__ __forceinline__ void storeB(float* dst, const u64* acc) {
    ulonglong2* p = (ulonglong2*)dst;
#pragma unroll
    for (int q = 0; q < 16; q++)
        p[q] = make_ulonglong2(acc[2 * q], acc[2 * q + 1]);
}

// ---------------- embedding: h0 = h @ embW + embB ----------------
__global__ __launch_bounds__(128) void k_embed(const float* __restrict__ h_in,
                                               const float* __restrict__ W,
                                               const float* __restrict__ b) {
    __shared__ float sW[INN * HH];
    __shared__ float sb[HH];
    for (int i = threadIdx.x; i < INN * HH; i += blockDim.x) sW[i] = W[i];
    for (int i = threadIdx.x; i < HH; i += blockDim.x) sb[i] = b[i];
    __syncthreads();
    int n = blockIdx.x * blockDim.x + threadIdx.x;
    if (n >= NN) return;
    u64 acc[32];
    loadB(acc, sb);
    const float4* hv = (const float4*)(h_in + (size_t)n * INN);
#pragma unroll
    for (int q = 0; q < INN / 4; q++) {
        float4 v = hv[q];
        fmaB(acc, pack2(v.x), sW + (4 * q + 0) * HH);
        fmaB(acc, pack2(v.y), sW + (4 * q + 1) * HH);
        fmaB(acc, pack2(v.z), sW + (4 * q + 2) * HH);
        fmaB(acc, pack2(v.w), sW + (4 * q + 3) * HH);
    }
    storeB(g_h0 + (size_t)n * HH, acc);
}

// ---------------- per-node precompute: A = h@W1a + b1, B = h@W1b ---------
#define PRE_SMEM_FLOATS (2 * HH * HH + HH)

__global__ __launch_bounds__(128) void k_pre(const float* __restrict__ h_in,
                                             const float* __restrict__ W1,
                                             const float* __restrict__ B1) {
    extern __shared__ float sm[];
    float* sWa = sm;                 // W1 rows 1..64   [64][64]
    float* sWb = sWa + HH * HH;      // W1 rows 65..128 [64][64]
    float* sb  = sWb + HH * HH;

    const int t = threadIdx.x;
    for (int i = t; i < HH * HH; i += 128) {
        sWa[i] = W1[(1 + (i >> 6)) * HH + (i & 63)];
        sWb[i] = W1[(1 + HH + (i >> 6)) * HH + (i & 63)];
    }
    for (int i = t; i < HH; i += 128) sb[i] = B1[i];
    __syncthreads();

    int n = blockIdx.x * 128 + t;
    if (n >= NN) return;

    float hv[HH];
    {
        const float4* p = (const float4*)(h_in + (size_t)n * HH);
#pragma unroll
        for (int q = 0; q < 16; q++) {
            float4 v = p[q];
            hv[4 * q] = v.x; hv[4 * q + 1] = v.y;
            hv[4 * q + 2] = v.z; hv[4 * q + 3] = v.w;
        }
    }
    u64 acc[32];
    loadB(acc, sb);
#pragma unroll
    for (int k = 0; k < HH; k++) fmaB(acc, pack2(hv[k]), sWa + k * HH);
    storeB(g_A + (size_t)n * HH, acc);

#pragma unroll
    for (int q = 0; q < 32; q++) acc[q] = 0ull;
#pragma unroll
    for (int k = 0; k < HH; k++) fmaB(acc, pack2(hv[k]), sWb + k * HH);
    storeB(g_B + (size_t)n * HH, acc);
}

// ---------------- degree count ----------------
__global__ void k_cnt(const int* __restrict__ row) {
    int e = blockIdx.x * blockDim.x + threadIdx.x;
    if (e < MM) atomicAdd(&g_cnt[row[e]], 1.0f);
}

// ---------------- fused edge kernel: quad-split + factored stage 1 -------
// smem: sW1e[9][64] (row0 = r2 weights, rows 1..8 = ef weights) | W2 | CW1 |
//       B2, CB1, CW2 | CB2
#define EDGE_SMEM_FLOATS (9 * HH + 2 * HH * HH + 3 * HH + 4)

__global__ __launch_bounds__(128, 3) void k_edge(
    const int* __restrict__ row, const int* __restrict__ col,
    const float* __restrict__ efea,
    const float* __restrict__ W1,
    const float* __restrict__ W2, const float* __restrict__ B2,
    const float* __restrict__ CW1, const float* __restrict__ CB1,
    const float* __restrict__ CW2, const float* __restrict__ CB2) {
    extern __shared__ float sm[];
    float* sW1e = sm;                  // [9][64] PERM4
    float* sW2  = sW1e + 9 * HH;       // [64][64] PERM4
    float* sCW1 = sW2 + HH * HH;       // [64][64] PERM4
    float* sB2  = sCW1 + HH * HH;
    float* sCB1 = sB2 + HH;
    float* sCW2 = sCB1 + HH;
    float* sCB2 = sCW2 + HH;

    const int t = threadIdx.x;
    for (int i = t; i < 9 * HH; i += 128) {
        int k = i >> 6, j = i & 63;
        int srcRow = (k == 0) ? 0 : (1 + 2 * HH + (k - 1));   // r2 row, then ef rows
        sW1e[(k << 6) + PERM4(j)] = W1[srcRow * HH + j];
    }
    for (int i = t; i < HH * HH; i += 128) {
        int k = i >> 6, j = i & 63;
        int p = (k << 6) + PERM4(j);
        sW2[p] = W2[i];
        sCW1[p] = CW1[i];
    }
    for (int i = t; i < HH; i += 128) {
        sB2[i] = B2[i]; sCB1[i] = CB1[i]; sCW2[i] = CW2[i];
    }
    if (t == 0) sCB2[0] = CB2[0];
    __syncthreads();

    const int lane = t & 31;
    const int h = lane & 3;
    const int qd = lane >> 2;
    const int e0 = blockIdx.x * 128 + ((t >> 5) << 5) + (qd << 2);
    const int4 rv = *(const int4*)(row + e0);
    const int4 cv = *(const int4*)(col + e0);
    const int r0 = rv.x, r1 = rv.y, r2i = rv.z, r3 = rv.w;
    const int c0 = cv.x, c1 = cv.y, c2 = cv.z, c3 = cv.w;

    const float rx0 = g_x[r0 * 3 + 0] - g_x[c0 * 3 + 0];
    const float ry0 = g_x[r0 * 3 + 1] - g_x[c0 * 3 + 1];
    const float rz0 = g_x[r0 * 3 + 2] - g_x[c0 * 3 + 2];
    const float rx1 = g_x[r1 * 3 + 0] - g_x[c1 * 3 + 0];
    const float ry1 = g_x[r1 * 3 + 1] - g_x[c1 * 3 + 1];
    const float rz1 = g_x[r1 * 3 + 2] - g_x[c1 * 3 + 2];
    const float rx2 = g_x[r2i * 3 + 0] - g_x[c2 * 3 + 0];
    const float ry2 = g_x[r2i * 3 + 1] - g_x[c2 * 3 + 1];
    const float rz2 = g_x[r2i * 3 + 2] - g_x[c2 * 3 + 2];
    const float rx3 = g_x[r3 * 3 + 0] - g_x[c3 * 3 + 0];
    const float ry3 = g_x[r3 * 3 + 1] - g_x[c3 * 3 + 1];
    const float rz3 = g_x[r3 * 3 + 2] - g_x[c3 * 3 + 2];
    const float s2_0 = rx0 * rx0 + ry0 * ry0 + rz0 * rz0;
    const float s2_1 = rx1 * rx1 + ry1 * ry1 + rz1 * rz1;
    const float s2_2 = rx2 * rx2 + ry2 * ry2 + rz2 * rz2;
    const float s2_3 = rx3 * rx3 + ry3 * ry3 + rz3 * rz3;

    const int h4 = h << 2;
    u64 a0[8], a1[8], a2[8], a3[8];

    // ---- stage 1 (factored): acc = A[r] + B[c]; += r2*w0; += ef @ Wef ----
    initAB(a0, r0, c0, h);
    initAB(a1, r1, c1, h);
    initAB(a2, r2i, c2, h);
    initAB(a3, r3, c3, h);
    fmaQuad(a0, a1, a2, a3, pack2(s2_0), pack2(s2_1), pack2(s2_2), pack2(s2_3),
            sW1e + h4);
    {
        const float4* ef0 = (const float4*)(efea + (size_t)e0 * EE);
        const float4* ef1 = (const float4*)(efea + (size_t)(e0 + 1) * EE);
        const float4* ef2 = (const float4*)(efea + (size_t)(e0 + 2) * EE);
        const float4* ef3 = (const float4*)(efea + (size_t)(e0 + 3) * EE);
#pragma unroll
        for (int q = 0; q < 2; q++) {
            float4 u0 = ef0[q], u1 = ef1[q], u2 = ef2[q], u3 = ef3[q];
            fmaQuad(a0, a1, a2, a3, pack2(u0.x), pack2(u1.x), pack2(u2.x), pack2(u3.x),
                    sW1e + ((1 + 4 * q + 0) << 6) + h4);
            fmaQuad(a0, a1, a2, a3, pack2(u0.y), pack2(u1.y), pack2(u2.y), pack2(u3.y),
                    sW1e + ((1 + 4 * q + 1) << 6) + h4);
            fmaQuad(a0, a1, a2, a3, pack2(u0.z), pack2(u1.z), pack2(u2.z), pack2(u3.z),
                    sW1e + ((1 + 4 * q + 2) << 6) + h4);
            fmaQuad(a0, a1, a2, a3, pack2(u0.w), pack2(u1.w), pack2(u2.w), pack2(u3.w),
                    sW1e + ((1 + 4 * q + 3) << 6) + h4);
        }
    }
    float hid0[16], hid1[16], hid2[16], hid3[16];
    siluQuarter(a0, hid0);
    siluQuarter(a1, hid1);
    siluQuarter(a2, hid2);
    siluQuarter(a3, hid3);

    // ---- stage 2: msg = silu(hid @ W2 + b2) ----
    loadQuarter(a0, sB2, h);
#pragma unroll
    for (int m = 0; m < 8; m++) { a1[m] = a0[m]; a2[m] = a0[m]; a3[m] = a0[m]; }
#pragma unroll
    for (int k = 0; k < HH; k++) {
        const int src = (lane & ~3) | (k >> 4);
        float s0 = __shfl_sync(0xffffffffu, hid0[k & 15], src);
        float s1 = __shfl_sync(0xffffffffu, hid1[k & 15], src);
        float s2 = __shfl_sync(0xffffffffu, hid2[k & 15], src);
        float s3 = __shfl_sync(0xffffffffu, hid3[k & 15], src);
        fmaQuad(a0, a1, a2, a3, pack2(s0), pack2(s1), pack2(s2), pack2(s3),
                sW2 + (k << 6) + h4);
    }
    float msg0[16], msg1[16], msg2[16], msg3[16];
    siluQuarter(a0, msg0);
    siluQuarter(a1, msg1);
    siluQuarter(a2, msg2);
    siluQuarter(a3, msg3);
    {
        const int jo = h << 4;
        float* am0 = &g_aggmsg[(size_t)r0 * HH + jo];
        float* am1 = &g_aggmsg[(size_t)r1 * HH + jo];
        float* am2 = &g_aggmsg[(size_t)r2i * HH + jo];
        float* am3 = &g_aggmsg[(size_t)r3 * HH + jo];
#pragma unroll
        for (int c = 0; c < 4; c++) {
            red4(am0 + 4 * c, msg0[4 * c], msg0[4 * c + 1], msg0[4 * c + 2], msg0[4 * c + 3]);
            red4(am1 + 4 * c, msg1[4 * c], msg1[4 * c + 1], msg1[4 * c + 2], msg1[4 * c + 3]);
            red4(am2 + 4 * c, msg2[4 * c], msg2[4 * c + 1], msg2[4 * c + 2], msg2[4 * c + 3]);
            red4(am3 + 4 * c, msg3[4 * c], msg3[4 * c + 1], msg3[4 * c + 2], msg3[4 * c + 3]);
        }
    }

    // ---- stage 3: cm = silu(msg @ CW1 + cb1) . CW2 + cb2 ----
    loadQuarter(a0, sCB1, h);
#pragma unroll
    for (int m = 0; m < 8; m++) { a1[m] = a0[m]; a2[m] = a0[m]; a3[m] = a0[m]; }
#pragma unroll
    for (int k = 0; k < HH; k++) {
        const int src = (lane & ~3) | (k >> 4);
        float s0 = __shfl_sync(0xffffffffu, msg0[k & 15], src);
        float s1 = __shfl_sync(0xffffffffu, msg1[k & 15], src);
        float s2 = __shfl_sync(0xffffffffu, msg2[k & 15], src);
        float s3 = __shfl_sync(0xffffffffu, msg3[k & 15], src);
        fmaQuad(a0, a1, a2, a3, pack2(s0), pack2(s1), pack2(s2), pack2(s3),
                sCW1 + (k << 6) + h4);
    }
    float cm0 = 0.0f, cm1 = 0.0f, cm2 = 0.0f, cm3 = 0.0f;
#pragma unroll
    for (int m = 0; m < 8; m++) {
        const int j = (h << 4) + 2 * m;
        const float wA = sCW2[j], wB = sCW2[j + 1];
        float x, y;
        unpack2(a0[m], x, y); cm0 += silu_f(x) * wA + silu_f(y) * wB;
        unpack2(a1[m], x, y); cm1 += silu_f(x) * wA + silu_f(y) * wB;
        unpack2(a2[m], x, y); cm2 += silu_f(x) * wA + silu_f(y) * wB;
        unpack2(a3[m], x, y); cm3 += silu_f(x) * wA + silu_f(y) * wB;
    }
    cm0 += __shfl_xor_sync(0xffffffffu, cm0, 1);
    cm0 += __shfl_xor_sync(0xffffffffu, cm0, 2);
    cm1 += __shfl_xor_sync(0xffffffffu, cm1, 1);
    cm1 += __shfl_xor_sync(0xffffffffu, cm1, 2);
    cm2 += __shfl_xor_sync(0xffffffffu, cm2, 1);
    cm2 += __shfl_xor_sync(0xffffffffu, cm2, 2);
    cm3 += __shfl_xor_sync(0xffffffffu, cm3, 1);
    cm3 += __shfl_xor_sync(0xffffffffu, cm3, 2);
    const float cb2v = sCB2[0];
    float fx, fy, fz;
    int re;
    if (h == 0)      { float c = cm0 + cb2v; fx = rx0 * c; fy = ry0 * c; fz = rz0 * c; re = r0; }
    else if (h == 1) { float c = cm1 + cb2v; fx = rx1 * c; fy = ry1 * c; fz = rz1 * c; re = r1; }
    else if (h == 2) { float c = cm2 + cb2v; fx = rx2 * c; fy = ry2 * c; fz = rz2 * c; re = r2i; }
    else             { float c = cm3 + cb2v; fx = rx3 * c; fy = ry3 * c; fz = rz3 * c; re = r3; }
    red4(&g_aggf[(size_t)re * 4], fx, fy, fz, 0.0f);
}

// ---------------- node kernel: pair-split, 2 nodes per lane-pair ---------
#define NODE_SMEM_FLOATS (2 * HH * HH + HH * HH + 2 * HH)

__global__ __launch_bounds__(128, 3) void k_node(
    const float* __restrict__ h_in, float* __restrict__ h_out,
    const float* __restrict__ NW1, const float* __restrict__ NB1,
    const float* __restrict__ NW2, const float* __restrict__ NB2,
    float* __restrict__ out_x, float* __restrict__ out_h, int writeOut) {
    extern __shared__ float sm[];
    float* sW1 = sm;                  // [128][64] PERM-interleaved
    float* sW2 = sW1 + 2 * HH * HH;   // [64][64]
    float* sB1 = sW2 + HH * HH;
    float* sB2 = sB1 + HH;

    const int t = threadIdx.x;
    for (int i = t; i < 2 * HH * HH; i += 128) {
        int k = i >> 6, j = i & 63;
        sW1[(k << 6) + PERM(j)] = NW1[i];
    }
    for (int i = t; i < HH * HH; i += 128) {
        int k = i >> 6, j = i & 63;
        sW2[(k << 6) + PERM(j)] = NW2[i];
    }
    for (int i = t; i < HH; i += 128) { sB1[i] = NB1[i]; sB2[i] = NB2[i]; }
    __syncthreads();

    const int lane = t & 31;
    const int h = lane & 1;
    int n0 = (blockIdx.x * 64 + ((t >> 5) << 4) + (lane >> 1)) * 2;
    const bool valid = (n0 < NN);
    if (!valid) n0 = NN - 2;
    const int n1 = n0 + 1;
    const int h4 = h << 2;

    u64 a0[16], a1[16];
    loadHalf(a0, sB1, h);
#pragma unroll
    for (int m = 0; m < 16; m++) a1[m] = a0[m];
    {
        const float4* p0 = (const float4*)(h_in + (size_t)n0 * HH);
        const float4* p1 = (const float4*)(h_in + (size_t)n1 * HH);
#pragma unroll
        for (int q = 0; q < 16; q++) {
            float4 u = p0[q], v = p1[q];
            fmaPair(a0, a1, pack2(u.x), pack2(v.x), sW1 + ((4 * q + 0) << 6) + h4);
            fmaPair(a0, a1, pack2(u.y), pack2(v.y), sW1 + ((4 * q + 1) << 6) + h4);
            fmaPair(a0, a1, pack2(u.z), pack2(v.z), sW1 + ((4 * q + 2) << 6) + h4);
            fmaPair(a0, a1, pack2(u.w), pack2(v.w), sW1 + ((4 * q + 3) << 6) + h4);
        }
        const float4* m0 = (const float4*)(g_aggmsg + (size_t)n0 * HH);
        const float4* m1 = (const float4*)(g_aggmsg + (size_t)n1 * HH);
#pragma unroll
        for (int q = 0; q < 16; q++) {
            float4 u = m0[q], v = m1[q];
            fmaPair(a0, a1, pack2(u.x), pack2(v.x), sW1 + ((HH + 4 * q + 0) << 6) + h4);
            fmaPair(a0, a1, pack2(u.y), pack2(v.y), sW1 + ((HH + 4 * q + 1) << 6) + h4);
            fmaPair(a0, a1, pack2(u.z), pack2(v.z), sW1 + ((HH + 4 * q + 2) << 6) + h4);
            fmaPair(a0, a1, pack2(u.w), pack2(v.w), sW1 + ((HH + 4 * q + 3) << 6) + h4);
        }
    }
    float hid0[32], hid1[32];
    siluHalf(a0, hid0);
    siluHalf(a1, hid1);

    loadHalf(a0, sB2, h);
#pragma unroll
    for (int m = 0; m < 16; m++) a1[m] = a0[m];
#pragma unroll
    for (int k = 0; k < HH; k++) {
        const int src = (lane & ~1) | (k >> 5);
        float s0 = __shfl_sync(0xffffffffu, hid0[k & 31], src);
        float s1 = __shfl_sync(0xffffffffu, hid1[k & 31], src);
        fmaPair(a0, a1, pack2(s0), pack2(s1), sW2 + (k << 6) + h4);
    }

    if (valid) {
        const int jo = h << 5;
        ulonglong2* o0 = (ulonglong2*)(h_out + (size_t)n0 * HH + jo);
        ulonglong2* o1 = (ulonglong2*)(h_out + (size_t)n1 * HH + jo);
#pragma unroll
        for (int c = 0; c < 8; c++) {
            o0[c] = make_ulonglong2(a0[2 * c], a0[2 * c + 1]);
            o1[c] = make_ulonglong2(a1[2 * c], a1[2 * c + 1]);
        }
        if (writeOut) {
            ulonglong2* q0 = (ulonglong2*)(out_h + (size_t)n0 * HH + jo);
            ulonglong2* q1 = (ulonglong2*)(out_h + (size_t)n1 * HH + jo);
#pragma unroll
            for (int c = 0; c < 8; c++) {
                q0[c] = make_ulonglong2(a0[2 * c], a0[2 * c + 1]);
                q1[c] = make_ulonglong2(a1[2 * c], a1[2 * c + 1]);
            }
        }
        const int n = n0 + h;
        float cnt = g_cnt[n];
        float inv = 1.0f / fmaxf(cnt, 1.0f);
#pragma unroll
        for (int d = 0; d < 3; d++) {
            float tot = g_aggf[(size_t)n * 4 + d] * inv;
            tot = fminf(fmaxf(tot, -100.0f), 100.0f);
            float nx = g_x[n * 3 + d] + tot;
            g_x[n * 3 + d] = nx;
            if (writeOut) out_x[n * 3 + d] = nx;
        }
    }
}

// ---------------- launch ----------------
extern "C" void kernel_launch(void* const* d_in, const int* in_sizes, int n_in,
                              void* d_out, int out_size) {
    const float* x    = (const float*)d_in[0];
    const float* h    = (const float*)d_in[1];
    const int*   row  = (const int*)d_in[2];
    const int*   col  = (const int*)d_in[3];
    const float* efea = (const float*)d_in[4];
    const float* embW = (const float*)d_in[5];
    const float* embB = (const float*)d_in[6];
    const float* eW1  = (const float*)d_in[7];
    const float* eB1  = (const float*)d_in[8];
    const float* eW2  = (const float*)d_in[9];
    const float* eB2  = (const float*)d_in[10];
    const float* cW1  = (const float*)d_in[11];
    const float* cB1  = (const float*)d_in[12];
    const float* cW2  = (const float*)d_in[13];
    const float* cB2  = (const float*)d_in[14];
    const float* nW1  = (const float*)d_in[15];
    const float* nB1  = (const float*)d_in[16];
    const float* nW2  = (const float*)d_in[17];
    const float* nB2  = (const float*)d_in[18];
    float* out = (float*)d_out;

    void *p_x, *p_h0, *p_h1, *p_am, *p_af, *p_cnt;
    cudaGetSymbolAddress(&p_x, g_x);
    cudaGetSymbolAddress(&p_h0, g_h0);
    cudaGetSymbolAddress(&p_h1, g_h1);
    cudaGetSymbolAddress(&p_am, g_aggmsg);
    cudaGetSymbolAddress(&p_af, g_aggf);
    cudaGetSymbolAddress(&p_cnt, g_cnt);

    const int edge_smem = EDGE_SMEM_FLOATS * sizeof(float);
    const int node_smem = NODE_SMEM_FLOATS * sizeof(float);
    const int pre_smem  = PRE_SMEM_FLOATS * sizeof(float);
    cudaFuncSetAttribute(k_edge, cudaFuncAttributeMaxDynamicSharedMemorySize, edge_smem);
    cudaFuncSetAttribute(k_node, cudaFuncAttributeMaxDynamicSharedMemorySize, node_smem);
    cudaFuncSetAttribute(k_pre,  cudaFuncAttributeMaxDynamicSharedMemorySize, pre_smem);

    cudaMemcpyAsync(p_x, x, NN * 3 * sizeof(float), cudaMemcpyDeviceToDevice, 0);
    cudaMemsetAsync(p_cnt, 0, NN * sizeof(float), 0);
    k_cnt<<<(MM + 255) / 256, 256>>>(row);
    k_embed<<<(NN + 127) / 128, 128>>>(h, embW, embB);

    float* hbuf[2] = {(float*)p_h0, (float*)p_h1};
    float* out_x = out;
    float* out_h = out + (size_t)NN * 3;

    const int node_grid = (NN / 2 + 63) / 64;   // 391

    for (int i = 0; i < LL; i++) {
        cudaMemsetAsync(p_am, 0, (size_t)NN * HH * sizeof(float), 0);
        cudaMemsetAsync(p_af, 0, (size_t)NN * 4 * sizeof(float), 0);
        k_pre<<<(NN + 127) / 128, 128, pre_smem>>>(
            hbuf[i & 1], eW1 + (size_t)i * DIN * HH, eB1 + (size_t)i * HH);
        k_edge<<<MM / 128, 128, edge_smem>>>(
            row, col, efea,
            eW1 + (size_t)i * DIN * HH,
            eW2 + (size_t)i * HH * HH,  eB2 + (size_t)i * HH,
            cW1 + (size_t)i * HH * HH,  cB1 + (size_t)i * HH,
            cW2 + (size_t)i * HH,       cB2 + (size_t)i * 1);
        k_node<<<node_grid, 128, node_smem>>>(
            hbuf[i & 1], hbuf[(i + 1) & 1],
            nW1 + (size_t)i * 2 * HH * HH, nB1 + (size_t)i * HH,
            nW2 + (size_t)i * HH * HH,     nB2 + (size_t)i * HH,
            out_x, out_h, (i == LL - 1) ? 1 : 0);
    }
    (void)in_sizes; (void)n_in; (void)out_size;
}

// round 9
// speedup vs baseline: 6.3661x; 1.0182x over previous
#include <cuda_runtime.h>

#define NN 50000
#define MM 800000
#define HH 64
#define EE 8
#define INN 16
#define DIN 137  // 1 + 2*H + E
#define LL 2

typedef unsigned long long u64;
typedef unsigned int u32;

// ---------------- device scratch (no allocs allowed) ----------------
__device__ float g_h0[NN * HH];
__device__ float g_h1[NN * HH];
__device__ float g_x[NN * 3];
__device__ float g_aggmsg[NN * HH];
__device__ float g_aggf[NN * 4];
__device__ float g_cnt[NN];
__device__ float g_A[NN * HH];     // h @ W1[1:65] + b1
__device__ float g_B[NN * HH];     // h @ W1[65:129]

__device__ __forceinline__ float silu_f(float v) {
    return __fdividef(v, 1.0f + __expf(-v));
}
__device__ __forceinline__ u64 pack2(float s) {
    u64 r; asm("mov.b64 %0, {%1, %1};" : "=l"(r) : "f"(s)); return r;
}
__device__ __forceinline__ void unpack2(u64 v, float& lo, float& hi) {
    asm("mov.b64 {%0, %1}, %2;" : "=f"(lo), "=f"(hi) : "l"(v));
}
__device__ __forceinline__ void fma2(u64& acc, u64 w, u64 s) {
    asm("fma.rn.f32x2 %0, %1, %2, %0;" : "+l"(acc) : "l"(w), "l"(s));
}
__device__ __forceinline__ void add2(u64& acc, u64 v) {
    asm("add.rn.f32x2 %0, %1, %0;" : "+l"(acc) : "l"(v));
}
__device__ __forceinline__ void red4(float* p, float a, float b, float c, float d) {
    asm volatile("red.global.add.v4.f32 [%0], {%1, %2, %3, %4};"
                 :: "l"(p), "f"(a), "f"(b), "f"(c), "f"(d) : "memory");
}
__host__ __device__ __forceinline__ int PERM(int j) {
    return (((j & 31) >> 2) << 3) + ((j >> 5) << 2) + (j & 3);
}
__host__ __device__ __forceinline__ int PERM4(int j) {
    return (((j & 15) >> 2) << 4) + ((j >> 4) << 2) + (j & 3);
}

// ---- pair helpers (k_node)
__device__ __forceinline__ void fmaPair(u64* a0, u64* a1, u64 s0, u64 s1,
                                        const float* wh) {
#pragma unroll
    for (int c = 0; c < 8; c++) {
        ulonglong2 t = *reinterpret_cast<const ulonglong2*>(wh + (c << 3));
        fma2(a0[2 * c],     t.x, s0);
        fma2(a0[2 * c + 1], t.y, s0);
        fma2(a1[2 * c],     t.x, s1);
        fma2(a1[2 * c + 1], t.y, s1);
    }
}
__device__ __forceinline__ void loadHalf(u64* a, const float* b, int h) {
    const ulonglong2* p = reinterpret_cast<const ulonglong2*>(b + (h << 5));
#pragma unroll
    for (int c = 0; c < 8; c++) {
        ulonglong2 v = p[c];
        a[2 * c] = v.x; a[2 * c + 1] = v.y;
    }
}
__device__ __forceinline__ void siluHalf(const u64* a, float* f) {
#pragma unroll
    for (int q = 0; q < 16; q++) {
        float x, y; unpack2(a[q], x, y);
        f[2 * q] = silu_f(x); f[2 * q + 1] = silu_f(y);
    }
}
// ---- quad helpers (edge)
__device__ __forceinline__ void fmaQuad(u64* a0, u64* a1, u64* a2, u64* a3,
                                        u64 s0, u64 s1, u64 s2, u64 s3,
                                        const float* wh) {
#pragma unroll
    for (int c = 0; c < 4; c++) {
        ulonglong2 t = *reinterpret_cast<const ulonglong2*>(wh + (c << 4));
        fma2(a0[2 * c], t.x, s0); fma2(a0[2 * c + 1], t.y, s0);
        fma2(a1[2 * c], t.x, s1); fma2(a1[2 * c + 1], t.y, s1);
        fma2(a2[2 * c], t.x, s2); fma2(a2[2 * c + 1], t.y, s2);
        fma2(a3[2 * c], t.x, s3); fma2(a3[2 * c + 1], t.y, s3);
    }
}
__device__ __forceinline__ void loadQuarter(u64* a, const float* b, int h) {
    const ulonglong2* p = reinterpret_cast<const ulonglong2*>(b + (h << 4));
#pragma unroll
    for (int c = 0; c < 4; c++) {
        ulonglong2 v = p[c];
        a[2 * c] = v.x; a[2 * c + 1] = v.y;
    }
}
__device__ __forceinline__ void siluQuarter(const u64* a, float* f) {
#pragma unroll
    for (int m = 0; m < 8; m++) {
        float x, y; unpack2(a[m], x, y);
        f[2 * m] = silu_f(x); f[2 * m + 1] = silu_f(y);
    }
}
__device__ __forceinline__ void initAB(u64* a, int r, int c, int h) {
    const ulonglong2* pa = (const ulonglong2*)(g_A + (size_t)r * HH + (h << 4));
    const ulonglong2* pb = (const ulonglong2*)(g_B + (size_t)c * HH + (h << 4));
#pragma unroll
    for (int q = 0; q < 4; q++) {
        ulonglong2 va = pa[q], vb = pb[q];
        add2(va.x, vb.x); add2(va.y, vb.y);
        a[2 * q] = va.x; a[2 * q + 1] = va.y;
    }
}
// ---- broadcast helpers
__device__ __forceinline__ void fmaB(u64* acc, u64 s2, const float* w) {
    const ulonglong2* w2 = reinterpret_cast<const ulonglong2*>(w);
#pragma unroll
    for (int q = 0; q < 16; q++) {
        ulonglong2 t = w2[q];
        fma2(acc[2 * q], t.x, s2); fma2(acc[2 * q + 1], t.y, s2);
    }
}
__device__ __forceinline__ void loadB(u64* acc, const float* b) {
    const ulonglong2* p = reinterpret_cast<const ulonglong2*>(b);
#pragma unroll
    for (int q = 0; q < 16; q++) {
        ulonglong2 v = p[q];
        acc[2 * q] = v.x; acc[2 * q + 1] = v.y;
    }
}
__device__ __forceinline__ void storeB(float* dst, const u64* acc) {
    ulonglong2* p = (ulonglong2*)dst;
#pragma unroll
    for (int q = 0; q < 16; q++)
        p[q] = make_ulonglong2(acc[2 * q], acc[2 * q + 1]);
}

// ---------------- embedding ----------------
__global__ __launch_bounds__(128) void k_embed(const float* __restrict__ h_in,
                                               const float* __restrict__ W,
                                               const float* __restrict__ b) {
    __shared__ float sW[INN * HH];
    __shared__ float sb[HH];
    for (int i = threadIdx.x; i < INN * HH; i += blockDim.x) sW[i] = W[i];
    for (int i = threadIdx.x; i < HH; i += blockDim.x) sb[i] = b[i];
    __syncthreads();
    int n = blockIdx.x * blockDim.x + threadIdx.x;
    if (n >= NN) return;
    u64 acc[32];
    loadB(acc, sb);
    const float4* hv = (const float4*)(h_in + (size_t)n * INN);
#pragma unroll
    for (int q = 0; q < INN / 4; q++) {
        float4 v = hv[q];
        fmaB(acc, pack2(v.x), sW + (4 * q + 0) * HH);
        fmaB(acc, pack2(v.y), sW + (4 * q + 1) * HH);
        fmaB(acc, pack2(v.z), sW + (4 * q + 2) * HH);
        fmaB(acc, pack2(v.w), sW + (4 * q + 3) * HH);
    }
    storeB(g_h0 + (size_t)n * HH, acc);
}

// ---------------- per-node precompute ----------------
#define PRE_SMEM_FLOATS (2 * HH * HH + HH)
__global__ __launch_bounds__(128) void k_pre(const float* __restrict__ h_in,
                                             const float* __restrict__ W1,
                                             const float* __restrict__ B1) {
    extern __shared__ float sm[];
    float* sWa = sm;
    float* sWb = sWa + HH * HH;
    float* sb  = sWb + HH * HH;
    const int t = threadIdx.x;
    for (int i = t; i < HH * HH; i += 128) {
        sWa[i] = W1[(1 + (i >> 6)) * HH + (i & 63)];
        sWb[i] = W1[(1 + HH + (i >> 6)) * HH + (i & 63)];
    }
    for (int i = t; i < HH; i += 128) sb[i] = B1[i];
    __syncthreads();
    int n = blockIdx.x * 128 + t;
    if (n >= NN) return;
    float hv[HH];
    {
        const float4* p = (const float4*)(h_in + (size_t)n * HH);
#pragma unroll
        for (int q = 0; q < 16; q++) {
            float4 v = p[q];
            hv[4 * q] = v.x; hv[4 * q + 1] = v.y;
            hv[4 * q + 2] = v.z; hv[4 * q + 3] = v.w;
        }
    }
    u64 acc[32];
    loadB(acc, sb);
#pragma unroll
    for (int k = 0; k < HH; k++) fmaB(acc, pack2(hv[k]), sWa + k * HH);
    storeB(g_A + (size_t)n * HH, acc);
#pragma unroll
    for (int q = 0; q < 32; q++) acc[q] = 0ull;
#pragma unroll
    for (int k = 0; k < HH; k++) fmaB(acc, pack2(hv[k]), sWb + k * HH);
    storeB(g_B + (size_t)n * HH, acc);
}

// ---------------- degree count ----------------
__global__ void k_cnt(const int* __restrict__ row) {
    int e = blockIdx.x * blockDim.x + threadIdx.x;
    if (e < MM) atomicAdd(&g_cnt[row[e]], 1.0f);
}

// ===== edge kernel: 256 thr, quad-split, smem-staged transposed operands ==
// smem floats:
//   sW1e[9*64] | sW2[64*64] | sCW1[64*64] | sB2,sCB1,sCW2 (64 ea) | sCB2(4) |
//   stage[8 warps][64 rows][32 floats]
#define EDGE_SMEM_FLOATS (9 * HH + 2 * HH * HH + 3 * HH + 4 + 8 * HH * 32)

__global__ __launch_bounds__(256, 2) void k_edge(
    const int* __restrict__ row, const int* __restrict__ col,
    const float* __restrict__ efea,
    const float* __restrict__ W1,
    const float* __restrict__ W2, const float* __restrict__ B2,
    const float* __restrict__ CW1, const float* __restrict__ CB1,
    const float* __restrict__ CW2, const float* __restrict__ CB2) {
    extern __shared__ float sm[];
    float* sW1e = sm;                  // [9][64] PERM4
    float* sW2p = sW1e + 9 * HH;       // [64][64] PERM4
    float* sCW1 = sW2p + HH * HH;      // [64][64] PERM4
    float* sB2  = sCW1 + HH * HH;
    float* sCB1 = sB2 + HH;
    float* sCW2 = sCB1 + HH;
    float* sCB2 = sCW2 + HH;
    float* sStg = sCB2 + 4;            // 8 * 2048

    const int t = threadIdx.x;
    for (int i = t; i < 9 * HH; i += 256) {
        int k = i >> 6, j = i & 63;
        int srcRow = (k == 0) ? 0 : (1 + 2 * HH + (k - 1));
        sW1e[(k << 6) + PERM4(j)] = W1[srcRow * HH + j];
    }
    for (int i = t; i < HH * HH; i += 256) {
        int k = i >> 6, j = i & 63;
        int p = (k << 6) + PERM4(j);
        sW2p[p] = W2[i];
        sCW1[p] = CW1[i];
    }
    for (int i = t; i < HH; i += 256) {
        sB2[i] = B2[i]; sCB1[i] = CB1[i]; sCW2[i] = CW2[i];
    }
    if (t == 0) sCB2[0] = CB2[0];
    __syncthreads();

    const int wid = t >> 5, lane = t & 31;
    const int h = lane & 3, qd = lane >> 2, h4 = h << 2;
    float4* stW = (float4*)(sStg + wid * (HH * 32));  // [64 rows][8 float4]

    const int e0 = blockIdx.x * 256 + (wid << 5) + (qd << 2);
    const int4 rv = *(const int4*)(row + e0);
    const int4 cv = *(const int4*)(col + e0);
    const int r0 = rv.x, r1 = rv.y, r2i = rv.z, r3 = rv.w;
    const int c0 = cv.x, c1 = cv.y, c2 = cv.z, c3 = cv.w;

    const float rx0 = g_x[r0 * 3 + 0] - g_x[c0 * 3 + 0];
    const float ry0 = g_x[r0 * 3 + 1] - g_x[c0 * 3 + 1];
    const float rz0 = g_x[r0 * 3 + 2] - g_x[c0 * 3 + 2];
    const float rx1 = g_x[r1 * 3 + 0] - g_x[c1 * 3 + 0];
    const float ry1 = g_x[r1 * 3 + 1] - g_x[c1 * 3 + 1];
    const float rz1 = g_x[r1 * 3 + 2] - g_x[c1 * 3 + 2];
    const float rx2 = g_x[r2i * 3 + 0] - g_x[c2 * 3 + 0];
    const float ry2 = g_x[r2i * 3 + 1] - g_x[c2 * 3 + 1];
    const float rz2 = g_x[r2i * 3 + 2] - g_x[c2 * 3 + 2];
    const float rx3 = g_x[r3 * 3 + 0] - g_x[c3 * 3 + 0];
    const float ry3 = g_x[r3 * 3 + 1] - g_x[c3 * 3 + 1];
    const float rz3 = g_x[r3 * 3 + 2] - g_x[c3 * 3 + 2];
    const float s2_0 = rx0 * rx0 + ry0 * ry0 + rz0 * rz0;
    const float s2_1 = rx1 * rx1 + ry1 * ry1 + rz1 * rz1;
    const float s2_2 = rx2 * rx2 + ry2 * ry2 + rz2 * rz2;
    const float s2_3 = rx3 * rx3 + ry3 * ry3 + rz3 * rz3;

    // keep only this lane's own-edge geometry (edge qd*4 + h) for stage 3
    float sx, sy, sz;
    if (h == 0)      { sx = rx0; sy = ry0; sz = rz0; }
    else if (h == 1) { sx = rx1; sy = ry1; sz = rz1; }
    else if (h == 2) { sx = rx2; sy = ry2; sz = rz2; }
    else             { sx = rx3; sy = ry3; sz = rz3; }

    u64 a0[8], a1[8], a2[8], a3[8];

    // ---- stage 1 (factored): acc = A[r]+B[c] + r2*w0 + ef@Wef ----
    initAB(a0, r0, c0, h);
    initAB(a1, r1, c1, h);
    initAB(a2, r2i, c2, h);
    initAB(a3, r3, c3, h);
    fmaQuad(a0, a1, a2, a3, pack2(s2_0), pack2(s2_1), pack2(s2_2), pack2(s2_3),
            sW1e + h4);
    {
        const float4* ef0 = (const float4*)(efea + (size_t)e0 * EE);
        const float4* ef1 = (const float4*)(efea + (size_t)(e0 + 1) * EE);
        const float4* ef2 = (const float4*)(efea + (size_t)(e0 + 2) * EE);
        const float4* ef3 = (const float4*)(efea + (size_t)(e0 + 3) * EE);
#pragma unroll
        for (int q = 0; q < 2; q++) {
            float4 u0 = ef0[q], u1 = ef1[q], u2 = ef2[q], u3 = ef3[q];
            fmaQuad(a0, a1, a2, a3, pack2(u0.x), pack2(u1.x), pack2(u2.x), pack2(u3.x),
                    sW1e + ((1 + 4 * q + 0) << 6) + h4);
            fmaQuad(a0, a1, a2, a3, pack2(u0.y), pack2(u1.y), pack2(u2.y), pack2(u3.y),
                    sW1e + ((1 + 4 * q + 1) << 6) + h4);
            fmaQuad(a0, a1, a2, a3, pack2(u0.z), pack2(u1.z), pack2(u2.z), pack2(u3.z),
                    sW1e + ((1 + 4 * q + 2) << 6) + h4);
            fmaQuad(a0, a1, a2, a3, pack2(u0.w), pack2(u1.w), pack2(u2.w), pack2(u3.w),
                    sW1e + ((1 + 4 * q + 3) << 6) + h4);
        }
    }
    // silu, write hid to staging [k=j][edge]: row = h*16+m, chunk = qd
    {
        float f0[16], f1[16], f2[16], f3[16];
        siluQuarter(a0, f0);
        siluQuarter(a1, f1);
        siluQuarter(a2, f2);
        siluQuarter(a3, f3);
#pragma unroll
        for (int m = 0; m < 16; m++)
            stW[((h << 4) + m) * 8 + qd] = make_float4(f0[m], f1[m], f2[m], f3[m]);
    }
    __syncwarp();

    // ---- stage 2: msg = silu(hid @ W2 + b2) ----
    loadQuarter(a0, sB2, h);
#pragma unroll
    for (int m = 0; m < 8; m++) { a1[m] = a0[m]; a2[m] = a0[m]; a3[m] = a0[m]; }
#pragma unroll
    for (int k = 0; k < HH; k++) {
        float4 s = stW[k * 8 + qd];
        fmaQuad(a0, a1, a2, a3, pack2(s.x), pack2(s.y), pack2(s.z), pack2(s.w),
                sW2p + (k << 6) + h4);
    }
    __syncwarp();   // all hid reads done before staging overwrite
    {
        float m0[16], m1[16], m2[16], m3[16];
        siluQuarter(a0, m0);
        siluQuarter(a1, m1);
        siluQuarter(a2, m2);
        siluQuarter(a3, m3);
        const int jo = h << 4;
        float* am0 = &g_aggmsg[(size_t)r0 * HH + jo];
        float* am1 = &g_aggmsg[(size_t)r1 * HH + jo];
        float* am2 = &g_aggmsg[(size_t)r2i * HH + jo];
        float* am3 = &g_aggmsg[(size_t)r3 * HH + jo];
#pragma unroll
        for (int c = 0; c < 4; c++) {
            red4(am0 + 4 * c, m0[4 * c], m0[4 * c + 1], m0[4 * c + 2], m0[4 * c + 3]);
            red4(am1 + 4 * c, m1[4 * c], m1[4 * c + 1], m1[4 * c + 2], m1[4 * c + 3]);
            red4(am2 + 4 * c, m2[4 * c], m2[4 * c + 1], m2[4 * c + 2], m2[4 * c + 3]);
            red4(am3 + 4 * c, m3[4 * c], m3[4 * c + 1], m3[4 * c + 2], m3[4 * c + 3]);
        }
#pragma unroll
        for (int m = 0; m < 16; m++)
            stW[((h << 4) + m) * 8 + qd] = make_float4(m0[m], m1[m], m2[m], m3[m]);
    }
    __syncwarp();

    // ---- stage 3: cm = silu(msg @ CW1 + cb1) . CW2 + cb2 ----
    loadQuarter(a0, sCB1, h);
#pragma unroll
    for (int m = 0; m < 8; m++) { a1[m] = a0[m]; a2[m] = a0[m]; a3[m] = a0[m]; }
#pragma unroll
    for (int k = 0; k < HH; k++) {
        float4 s = stW[k * 8 + qd];
        fmaQuad(a0, a1, a2, a3, pack2(s.x), pack2(s.y), pack2(s.z), pack2(s.w),
                sCW1 + (k << 6) + h4);
    }
    float cm0 = 0.0f, cm1 = 0.0f, cm2 = 0.0f, cm3 = 0.0f;
#pragma unroll
    for (int m = 0; m < 8; m++) {
        const int j = (h << 4) + 2 * m;
        const float wA = sCW2[j], wB = sCW2[j + 1];
        float x, y;
        unpack2(a0[m], x, y); cm0 += silu_f(x) * wA + silu_f(y) * wB;
        unpack2(a1[m], x, y); cm1 += silu_f(x) * wA + silu_f(y) * wB;
        unpack2(a2[m], x, y); cm2 += silu_f(x) * wA + silu_f(y) * wB;
        unpack2(a3[m], x, y); cm3 += silu_f(x) * wA + silu_f(y) * wB;
    }
    cm0 += __shfl_xor_sync(0xffffffffu, cm0, 1);
    cm0 += __shfl_xor_sync(0xffffffffu, cm0, 2);
    cm1 += __shfl_xor_sync(0xffffffffu, cm1, 1);
    cm1 += __shfl_xor_sync(0xffffffffu, cm1, 2);
    cm2 += __shfl_xor_sync(0xffffffffu, cm2, 1);
    cm2 += __shfl_xor_sync(0xffffffffu, cm2, 2);
    cm3 += __shfl_xor_sync(0xffffffffu, cm3, 1);
    cm3 += __shfl_xor_sync(0xffffffffu, cm3, 2);
    const float cb2v = sCB2[0];
    float cm; int re;
    if (h == 0)      { cm = cm0 + cb2v; re = r0; }
    else if (h == 1) { cm = cm1 + cb2v; re = r1; }
    else if (h == 2) { cm = cm2 + cb2v; re = r2i; }
    else             { cm = cm3 + cb2v; re = r3; }
    red4(&g_aggf[(size_t)re * 4], sx * cm, sy * cm, sz * cm, 0.0f);
}

// ---------------- node kernel (pair-split) ----------------
#define NODE_SMEM_FLOATS (2 * HH * HH + HH * HH + 2 * HH)
__global__ __launch_bounds__(128, 3) void k_node(
    const float* __restrict__ h_in, float* __restrict__ h_out,
    const float* __restrict__ NW1, const float* __restrict__ NB1,
    const float* __restrict__ NW2, const float* __restrict__ NB2,
    float* __restrict__ out_x, float* __restrict__ out_h, int writeOut) {
    extern __shared__ float sm[];
    float* sW1 = sm;
    float* sW2 = sW1 + 2 * HH * HH;
    float* sB1 = sW2 + HH * HH;
    float* sB2 = sB1 + HH;
    const int t = threadIdx.x;
    for (int i = t; i < 2 * HH * HH; i += 128) {
        int k = i >> 6, j = i & 63;
        sW1[(k << 6) + PERM(j)] = NW1[i];
    }
    for (int i = t; i < HH * HH; i += 128) {
        int k = i >> 6, j = i & 63;
        sW2[(k << 6) + PERM(j)] = NW2[i];
    }
    for (int i = t; i < HH; i += 128) { sB1[i] = NB1[i]; sB2[i] = NB2[i]; }
    __syncthreads();

    const int lane = t & 31;
    const int h = lane & 1;
    int n0 = (blockIdx.x * 64 + ((t >> 5) << 4) + (lane >> 1)) * 2;
    const bool valid = (n0 < NN);
    if (!valid) n0 = NN - 2;
    const int n1 = n0 + 1;
    const int h4 = h << 2;

    u64 a0[16], a1[16];
    loadHalf(a0, sB1, h);
#pragma unroll
    for (int m = 0; m < 16; m++) a1[m] = a0[m];
    {
        const float4* p0 = (const float4*)(h_in + (size_t)n0 * HH);
        const float4* p1 = (const float4*)(h_in + (size_t)n1 * HH);
#pragma unroll
        for (int q = 0; q < 16; q++) {
            float4 u = p0[q], v = p1[q];
            fmaPair(a0, a1, pack2(u.x), pack2(v.x), sW1 + ((4 * q + 0) << 6) + h4);
            fmaPair(a0, a1, pack2(u.y), pack2(v.y), sW1 + ((4 * q + 1) << 6) + h4);
            fmaPair(a0, a1, pack2(u.z), pack2(v.z), sW1 + ((4 * q + 2) << 6) + h4);
            fmaPair(a0, a1, pack2(u.w), pack2(v.w), sW1 + ((4 * q + 3) << 6) + h4);
        }
        const float4* m0 = (const float4*)(g_aggmsg + (size_t)n0 * HH);
        const float4* m1 = (const float4*)(g_aggmsg + (size_t)n1 * HH);
#pragma unroll
        for (int q = 0; q < 16; q++) {
            float4 u = m0[q], v = m1[q];
            fmaPair(a0, a1, pack2(u.x), pack2(v.x), sW1 + ((HH + 4 * q + 0) << 6) + h4);
            fmaPair(a0, a1, pack2(u.y), pack2(v.y), sW1 + ((HH + 4 * q + 1) << 6) + h4);
            fmaPair(a0, a1, pack2(u.z), pack2(v.z), sW1 + ((HH + 4 * q + 2) << 6) + h4);
            fmaPair(a0, a1, pack2(u.w), pack2(v.w), sW1 + ((HH + 4 * q + 3) << 6) + h4);
        }
    }
    float hid0[32], hid1[32];
    siluHalf(a0, hid0);
    siluHalf(a1, hid1);

    loadHalf(a0, sB2, h);
#pragma unroll
    for (int m = 0; m < 16; m++) a1[m] = a0[m];
#pragma unroll
    for (int k = 0; k < HH; k++) {
        const int src = (lane & ~1) | (k >> 5);
        float s0 = __shfl_sync(0xffffffffu, hid0[k & 31], src);
        float s1 = __shfl_sync(0xffffffffu, hid1[k & 31], src);
        fmaPair(a0, a1, pack2(s0), pack2(s1), sW2 + (k << 6) + h4);
    }

    if (valid) {
        const int jo = h << 5;
        ulonglong2* o0 = (ulonglong2*)(h_out + (size_t)n0 * HH + jo);
        ulonglong2* o1 = (ulonglong2*)(h_out + (size_t)n1 * HH + jo);
#pragma unroll
        for (int c = 0; c < 8; c++) {
            o0[c] = make_ulonglong2(a0[2 * c], a0[2 * c + 1]);
            o1[c] = make_ulonglong2(a1[2 * c], a1[2 * c + 1]);
        }
        if (writeOut) {
            ulonglong2* q0 = (ulonglong2*)(out_h + (size_t)n0 * HH + jo);
            ulonglong2* q1 = (ulonglong2*)(out_h + (size_t)n1 * HH + jo);
#pragma unroll
            for (int c = 0; c < 8; c++) {
                q0[c] = make_ulonglong2(a0[2 * c], a0[2 * c + 1]);
                q1[c] = make_ulonglong2(a1[2 * c], a1[2 * c + 1]);
            }
        }
        const int n = n0 + h;
        float cnt = g_cnt[n];
        float inv = 1.0f / fmaxf(cnt, 1.0f);
#pragma unroll
        for (int d = 0; d < 3; d++) {
            float tot = g_aggf[(size_t)n * 4 + d] * inv;
            tot = fminf(fmaxf(tot, -100.0f), 100.0f);
            float nx = g_x[n * 3 + d] + tot;
            g_x[n * 3 + d] = nx;
            if (writeOut) out_x[n * 3 + d] = nx;
        }
    }
}

// ---------------- launch ----------------
extern "C" void kernel_launch(void* const* d_in, const int* in_sizes, int n_in,
                              void* d_out, int out_size) {
    const float* x    = (const float*)d_in[0];
    const float* h    = (const float*)d_in[1];
    const int*   row  = (const int*)d_in[2];
    const int*   col  = (const int*)d_in[3];
    const float* efea = (const float*)d_in[4];
    const float* embW = (const float*)d_in[5];
    const float* embB = (const float*)d_in[6];
    const float* eW1  = (const float*)d_in[7];
    const float* eB1  = (const float*)d_in[8];
    const float* eW2  = (const float*)d_in[9];
    const float* eB2  = (const float*)d_in[10];
    const float* cW1  = (const float*)d_in[11];
    const float* cB1  = (const float*)d_in[12];
    const float* cW2  = (const float*)d_in[13];
    const float* cB2  = (const float*)d_in[14];
    const float* nW1  = (const float*)d_in[15];
    const float* nB1  = (const float*)d_in[16];
    const float* nW2  = (const float*)d_in[17];
    const float* nB2  = (const float*)d_in[18];
    float* out = (float*)d_out;

    void *p_x, *p_h0, *p_h1, *p_am, *p_af, *p_cnt;
    cudaGetSymbolAddress(&p_x, g_x);
    cudaGetSymbolAddress(&p_h0, g_h0);
    cudaGetSymbolAddress(&p_h1, g_h1);
    cudaGetSymbolAddress(&p_am, g_aggmsg);
    cudaGetSymbolAddress(&p_af, g_aggf);
    cudaGetSymbolAddress(&p_cnt, g_cnt);

    const int edge_smem = EDGE_SMEM_FLOATS * sizeof(float);
    const int node_smem = NODE_SMEM_FLOATS * sizeof(float);
    const int pre_smem  = PRE_SMEM_FLOATS * sizeof(float);
    cudaFuncSetAttribute(k_edge, cudaFuncAttributeMaxDynamicSharedMemorySize, edge_smem);
    cudaFuncSetAttribute(k_node, cudaFuncAttributeMaxDynamicSharedMemorySize, node_smem);
    cudaFuncSetAttribute(k_pre,  cudaFuncAttributeMaxDynamicSharedMemorySize, pre_smem);

    cudaMemcpyAsync(p_x, x, NN * 3 * sizeof(float), cudaMemcpyDeviceToDevice, 0);
    cudaMemsetAsync(p_cnt, 0, NN * sizeof(float), 0);
    k_cnt<<<(MM + 255) / 256, 256>>>(row);
    k_embed<<<(NN + 127) / 128, 128>>>(h, embW, embB);

    float* hbuf[2] = {(float*)p_h0, (float*)p_h1};
    float* out_x = out;
    float* out_h = out + (size_t)NN * 3;
    const int node_grid = (NN / 2 + 63) / 64;   // 391

    for (int i = 0; i < LL; i++) {
        cudaMemsetAsync(p_am, 0, (size_t)NN * HH * sizeof(float), 0);
        cudaMemsetAsync(p_af, 0, (size_t)NN * 4 * sizeof(float), 0);
        k_pre<<<(NN + 127) / 128, 128, pre_smem>>>(
            hbuf[i & 1], eW1 + (size_t)i * DIN * HH, eB1 + (size_t)i * HH);
        k_edge<<<MM / 256, 256, edge_smem>>>(
            row, col, efea,
            eW1 + (size_t)i * DIN * HH,
            eW2 + (size_t)i * HH * HH,  eB2 + (size_t)i * HH,
            cW1 + (size_t)i * HH * HH,  cB1 + (size_t)i * HH,
            cW2 + (size_t)i * HH,       cB2 + (size_t)i * 1);
        k_node<<<node_grid, 128, node_smem>>>(
            hbuf[i & 1], hbuf[(i + 1) & 1],
            nW1 + (size_t)i * 2 * HH * HH, nB1 + (size_t)i * HH,
            nW2 + (size_t)i * HH * HH,     nB2 + (size_t)i * HH,
            out_x, out_h, (i == LL - 1) ? 1 : 0);
    }
    (void)in_sizes; (void)n_in; (void)out_size;
}